// round 6
// baseline (speedup 1.0000x reference)
#include <cuda_runtime.h>
#include <cuda_bf16.h>
#include <math.h>
#include <stdint.h>

// ---------------- problem constants ----------------
#define Nn 20000
#define Dd 128
#define Hh 256
#define Kk 16

// ---------------- grid constants -------------------
#define GG 24
#define NC (GG * GG * GG)        // 13824
#define XMIN (-6.0f)
#define CELL (0.5f)
#define INV_CELL (2.0f)
#define FINF 3.4e38f
#define FULLM 0xffffffffu

// ---------------- scratch (static device) ----------
__device__ int   g_cellOf[Nn];
__device__ int   g_cellCnt[NC];
__device__ int   g_cellStart[NC + 1];
__device__ int   g_cellCur[NC];
__device__ float4 g_pts[Nn];      // (x, y, z, sq) sorted by cell
__device__ int   g_ptIdx[Nn];     // original index, sorted by cell
__device__ int   g_knn[Nn * Kk];
__device__ int   g_deg[Nn];
__device__ float g_srcn[Nn];
__device__ __align__(16) float    g_bufH[Nn * Hh];
__device__ __align__(16) uint32_t g_bufS[Nn * Hh];
__device__ __align__(16) uint32_t g_wt2[Hh * Hh];

// ---------------- small helpers --------------------
__device__ __forceinline__ int cellc(float v) {
    int c = (int)floorf((v - XMIN) * INV_CELL);
    return min(max(c, 0), GG - 1);
}

__device__ __forceinline__ uint32_t pack_split(float v) {
    __nv_bfloat16 h = __float2bfloat16(v);
    float hf = __bfloat162float(h);
    __nv_bfloat16 l = __float2bfloat16(v - hf);
    unsigned short hs = *reinterpret_cast<unsigned short*>(&h);
    unsigned short ls = *reinterpret_cast<unsigned short*>(&l);
    return (uint32_t)hs | ((uint32_t)ls << 16);
}

__device__ __forceinline__ uint32_t smem_u32(const void* p) {
    uint32_t a;
    asm("{ .reg .u64 t; cvta.to.shared.u64 t, %1; cvt.u32.u64 %0, t; }"
        : "=r"(a) : "l"(p));
    return a;
}

__device__ __forceinline__ void ldsm4(uint32_t* r, uint32_t addr) {
    asm volatile("ldmatrix.sync.aligned.m8n8.x4.shared.b16 {%0,%1,%2,%3}, [%4];"
                 : "=r"(r[0]), "=r"(r[1]), "=r"(r[2]), "=r"(r[3]) : "r"(addr));
}

__device__ __forceinline__ void mma16816(float* c, const uint32_t* a,
                                         const uint32_t b0, const uint32_t b1) {
    asm volatile(
        "mma.sync.aligned.m16n8k16.row.col.f32.bf16.bf16.f32 "
        "{%0,%1,%2,%3}, {%4,%5,%6,%7}, {%8,%9}, {%0,%1,%2,%3};"
        : "+f"(c[0]), "+f"(c[1]), "+f"(c[2]), "+f"(c[3])
        : "r"(a[0]), "r"(a[1]), "r"(a[2]), "r"(a[3]), "r"(b0), "r"(b1));
}

// ---------------- setup kernels --------------------

__global__ void assign_kernel(const float* __restrict__ centers) {
    int i = blockIdx.x * blockDim.x + threadIdx.x;
    if (i >= Nn) return;
    float x = centers[3 * i], y = centers[3 * i + 1], z = centers[3 * i + 2];
    int cid = (cellc(z) * GG + cellc(y)) * GG + cellc(x);
    g_cellOf[i] = cid;
    atomicAdd(&g_cellCnt[cid], 1);
}

__global__ void scan_kernel() {
    const int per = 14;   // 1024*14 = 14336 >= NC
    int t = threadIdx.x;
    int base = t * per;
    int s = 0;
    for (int i = 0; i < per; i++) {
        int idx = base + i;
        s += (idx < NC) ? g_cellCnt[idx] : 0;
    }

    int lane = t & 31, w = t >> 5;
    int v = s;
    for (int o = 1; o < 32; o <<= 1) {
        int n = __shfl_up_sync(FULLM, v, o);
        if (lane >= o) v += n;
    }
    __shared__ int ws[32];
    if (lane == 31) ws[w] = v;
    __syncthreads();
    if (w == 0) {
        int xv = ws[lane];
        for (int o = 1; o < 32; o <<= 1) {
            int n = __shfl_up_sync(FULLM, xv, o);
            if (lane >= o) xv += n;
        }
        ws[lane] = xv;
    }
    __syncthreads();
    int excl = v - s + (w ? ws[w - 1] : 0);
    int run = excl;
    for (int i = 0; i < per; i++) {
        int idx = base + i;
        if (idx < NC) {
            int c = g_cellCnt[idx];
            g_cellStart[idx] = run;
            g_cellCur[idx] = run;
            run += c;
        }
    }
    if (t == 1023) g_cellStart[NC] = Nn;
}

__global__ void scatter_kernel(const float* __restrict__ centers) {
    int i = blockIdx.x * blockDim.x + threadIdx.x;
    if (i >= Nn) return;
    int cid = g_cellOf[i];
    int pos = atomicAdd(&g_cellCur[cid], 1);
    float x = centers[3 * i], y = centers[3 * i + 1], z = centers[3 * i + 2];
    float sq = fmaf(z, z, fmaf(y, y, x * x));
    g_pts[pos] = make_float4(x, y, z, sq);
    g_ptIdx[pos] = i;
}

// ---------------- warp-per-query exact kNN + cell pruning ----------------
__global__ void __launch_bounds__(256) knn_kernel() {
    int gw = (blockIdx.x * blockDim.x + threadIdx.x) >> 5;
    int lane = threadIdx.x & 31;
    if (gw >= Nn) return;
    float4 q = g_pts[gw];
    int orig = g_ptIdx[gw];
    float qx = q.x, qy = q.y, qz = q.z, qsq = q.w;
    int cx = cellc(qx), cy = cellc(qy), cz = cellc(qz);

    float ld = FINF;   // distributed list: lane j = j-th smallest d2
    int   li = 0;
    float gth = FINF;  // current 16th-best (uniform)

    int Rcov = max(max(max(cx, GG - 1 - cx), max(cy, GG - 1 - cy)),
                   max(cz, GG - 1 - cz));

    for (int R = 0; R <= Rcov; R++) {
        int zlo = max(cz - R, 0), zhi = min(cz + R, GG - 1);
        int ylo = max(cy - R, 0), yhi = min(cy + R, GG - 1);
        int xlo = max(cx - R, 0), xhi = min(cx + R, GG - 1);
        for (int z = zlo; z <= zhi; z++) {
            int adz = abs(z - cz);
            // min distance from q to z-slab of this cell layer
            float zl = XMIN + (float)z * CELL;
            float dzd = fmaxf(fmaxf(zl - qz, qz - (zl + CELL)), 0.0f);
            float dz2 = dzd * dzd;
            for (int y = ylo; y <= yhi; y++) {
                int dzy = max(adz, abs(y - cy));
                float yl = XMIN + (float)y * CELL;
                float dyd = fmaxf(fmaxf(yl - qy, qy - (yl + CELL)), 0.0f);
                float dzy2 = fmaf(dyd, dyd, dz2);
                if (dzy2 >= gth) continue;     // whole row pruned (uniform)
                int runs[2][2];
                int nruns = 0;
                if (dzy == R) {
                    runs[0][0] = xlo; runs[0][1] = xhi; nruns = 1;
                } else {
                    if (cx - R >= 0) { runs[nruns][0] = cx - R; runs[nruns][1] = cx - R; nruns++; }
                    if (cx + R < GG) { runs[nruns][0] = cx + R; runs[nruns][1] = cx + R; nruns++; }
                }
                int rowbase = (z * GG + y) * GG;
                for (int r = 0; r < nruns; r++) {
                    for (int xc = runs[r][0]; xc <= runs[r][1]; xc++) {
                        // per-cell prune
                        float xl = XMIN + (float)xc * CELL;
                        float dxd = fmaxf(fmaxf(xl - qx, qx - (xl + CELL)), 0.0f);
                        if (fmaf(dxd, dxd, dzy2) >= gth) continue;
                        int p0 = g_cellStart[rowbase + xc];
                        int p1 = g_cellStart[rowbase + xc + 1];
                        for (int pb = p0; pb < p1; pb += 32) {
                            int p = pb + lane;
                            float d2 = FINF;
                            int pid = 0;
                            if (p < p1) {
                                float4 c = g_pts[p];
                                float t1 = fmaf(qx, c.x, fmaf(qy, c.y, qz * c.z));
                                d2 = fmaf(-2.0f, t1, qsq + c.w);
                                pid = g_ptIdx[p];
                            }
                            unsigned mask = __ballot_sync(FULLM, d2 < gth);
                            while (mask) {
                                int src = __ffs(mask) - 1;
                                mask &= mask - 1;
                                float nd = __shfl_sync(FULLM, d2, src);
                                int   ni = __shfl_sync(FULLM, pid, src);
                                if (nd >= gth) continue;       // uniform
                                unsigned le = __ballot_sync(FULLM, ld <= nd);
                                int pos = __popc(le);
                                float pd = __shfl_up_sync(FULLM, ld, 1);
                                int   pi = __shfl_up_sync(FULLM, li, 1);
                                if (lane >= pos) { ld = pd; li = pi; }
                                if (lane == pos) { ld = nd; li = ni; }
                                gth = __shfl_sync(FULLM, ld, 15);
                            }
                        }
                    }
                }
            }
        }
        // stopping rule: gth is exact 16th best so far (uniform)
        if (gth < FINF) {
            float bx = fminf(qx - (XMIN + (float)(cx - R) * CELL),
                             (XMIN + (float)(cx + R + 1) * CELL) - qx);
            float by = fminf(qy - (XMIN + (float)(cy - R) * CELL),
                             (XMIN + (float)(cy + R + 1) * CELL) - qy);
            float bz = fminf(qz - (XMIN + (float)(cz - R) * CELL),
                             (XMIN + (float)(cz + R + 1) * CELL) - qz);
            float b = fmaxf(fminf(bx, fminf(by, bz)), 0.0f);
            if (gth <= b * b) break;
        }
    }

    if (lane < Kk) g_knn[orig * Kk + lane] = li;
}

__global__ void deg_kernel() {
    int e = blockIdx.x * blockDim.x + threadIdx.x;
    if (e < Nn * Kk) atomicAdd(&g_deg[g_knn[e]], 1);
}

__global__ void srcn_kernel() {
    int i = blockIdx.x * blockDim.x + threadIdx.x;
    if (i < Nn) g_srcn[i] = rsqrtf(fmaxf((float)g_deg[i], 1.0f));
}

// split-transpose of W[k][Hh] -> Wt2[n][Kd] packed (hi | lo<<16)
__global__ void convw_kernel(const float* __restrict__ W, int Kd) {
    int i = blockIdx.x * blockDim.x + threadIdx.x;
    if (i >= Kd * Hh) return;
    int k = i % Kd;
    int n = i / Kd;
    g_wt2[(size_t)n * Kd + k] = pack_split(W[(size_t)k * Hh + n]);
}

// agg[i, :] = 0.25 * sum_k h[knn[i,k], :] * srcn[knn[i,k]]  -> packed split
// float4 vectorized; TPN = F/4 threads per node, 256-thread blocks.
template <int F>
__global__ void __launch_bounds__(256) aggregate_kernel(
    const float* __restrict__ Hin, uint32_t* __restrict__ Sout) {
    const int TPN = F / 4;
    const int NPB = 256 / TPN;
    __shared__ int   jj[NPB][Kk];
    __shared__ float ss[NPB][Kk];
    int g = threadIdx.x / TPN;
    int t = threadIdx.x % TPN;
    int node = blockIdx.x * NPB + g;
    bool ok = node < Nn;
    if (ok && t < Kk) {
        int j = g_knn[node * Kk + t];
        jj[g][t] = j;
        ss[g][t] = g_srcn[j];
    }
    __syncthreads();
    if (!ok) return;
    float4 acc = make_float4(0.f, 0.f, 0.f, 0.f);
#pragma unroll
    for (int k = 0; k < Kk; k++) {
        const float4* row = (const float4*)(Hin + (size_t)jj[g][k] * F);
        float4 v = row[t];
        float s = ss[g][k];
        acc.x = fmaf(v.x, s, acc.x);
        acc.y = fmaf(v.y, s, acc.y);
        acc.z = fmaf(v.z, s, acc.z);
        acc.w = fmaf(v.w, s, acc.w);
    }
    uint4 o;
    o.x = pack_split(acc.x * 0.25f);
    o.y = pack_split(acc.y * 0.25f);
    o.z = pack_split(acc.z * 0.25f);
    o.w = pack_split(acc.w * 0.25f);
    *(uint4*)(Sout + (size_t)node * F + t * 4) = o;
}

// ---------------- tensor-core GEMM -----------------
#define BM 128
#define BN 128
#define BK 16
#define LDA 56

__global__ void __launch_bounds__(256, 2) mma_gemm_kernel(
    const uint32_t* __restrict__ A2, const uint32_t* __restrict__ B2,
    const float* __restrict__ bias, float* __restrict__ C,
    int M, int Kd, int Nc) {
    __shared__ __align__(16) uint16_t As[BM * LDA];
    __shared__ __align__(16) uint16_t Bs[BN * LDA];

    int t = threadIdx.x;
    int lane = t & 31;
    int wid = t >> 5;
    int m0 = blockIdx.y * BM;
    int n0 = blockIdx.x * BN;

    int wm = wid & 3;
    int wn = wid >> 2;
    int m_base = wm * 32;
    int n_base = wn * 64;

    uint32_t as_base = smem_u32(As);
    uint32_t bs_base = smem_u32(Bs);

    uint32_t aaddr[2], baddr[4];
#pragma unroll
    for (int f = 0; f < 2; f++) {
        int row = m_base + f * 16 + (lane & 7) + (lane & 8);
        int koff = (lane & 16) ? 16 : 0;
        aaddr[f] = as_base + row * (LDA * 2) + koff;
    }
#pragma unroll
    for (int p = 0; p < 4; p++) {
        int row = n_base + p * 16 + (lane & 7) + ((lane & 16) >> 1);
        int koff = (lane & 8) ? 16 : 0;
        baddr[p] = bs_base + row * (LDA * 2) + koff;
    }

    float acc[2][8][4];
#pragma unroll
    for (int f = 0; f < 2; f++)
#pragma unroll
        for (int nf = 0; nf < 8; nf++)
#pragma unroll
            for (int c = 0; c < 4; c++) acc[f][nf][c] = 0.0f;

    uint32_t* As32 = (uint32_t*)As;
    uint32_t* Bs32 = (uint32_t*)Bs;

    const int steps = Kd / BK;
    for (int s = 0; s < steps; s++) {
        int k0 = s * BK;
#pragma unroll
        for (int v = 0; v < 2; v++) {
            int vec = t + v * 256;
            int row = vec >> 2, q = vec & 3;
            int gm = m0 + row;
            uint4 d = make_uint4(0u, 0u, 0u, 0u);
            if (gm < M)
                d = *(const uint4*)(A2 + (size_t)gm * Kd + k0 + q * 4);
            uint32_t h0 = d.x & 0xffffu, l0 = d.x >> 16;
            uint32_t h1 = d.y & 0xffffu, l1 = d.y >> 16;
            uint32_t h2 = d.z & 0xffffu, l2 = d.z >> 16;
            uint32_t h3 = d.w & 0xffffu, l3 = d.w >> 16;
            uint32_t hp0 = h0 | (h1 << 16), hp1 = h2 | (h3 << 16);
            uint32_t lp0 = l0 | (l1 << 16), lp1 = l2 | (l3 << 16);
            int b32 = row * (LDA / 2) + 2 * q;
            As32[b32 + 0] = hp0;  As32[b32 + 1] = hp1;
            As32[b32 + 8] = lp0;  As32[b32 + 9] = lp1;
            As32[b32 + 16] = hp0; As32[b32 + 17] = hp1;
        }
#pragma unroll
        for (int v = 0; v < 2; v++) {
            int vec = t + v * 256;
            int row = vec >> 2, q = vec & 3;
            uint4 d = *(const uint4*)(B2 + (size_t)(n0 + row) * Kd + k0 + q * 4);
            uint32_t h0 = d.x & 0xffffu, l0 = d.x >> 16;
            uint32_t h1 = d.y & 0xffffu, l1 = d.y >> 16;
            uint32_t h2 = d.z & 0xffffu, l2 = d.z >> 16;
            uint32_t h3 = d.w & 0xffffu, l3 = d.w >> 16;
            uint32_t hp0 = h0 | (h1 << 16), hp1 = h2 | (h3 << 16);
            uint32_t lp0 = l0 | (l1 << 16), lp1 = l2 | (l3 << 16);
            int b32 = row * (LDA / 2) + 2 * q;
            Bs32[b32 + 0] = hp0;  Bs32[b32 + 1] = hp1;
            Bs32[b32 + 8] = hp0;  Bs32[b32 + 9] = hp1;
            Bs32[b32 + 16] = lp0; Bs32[b32 + 17] = lp1;
        }
        __syncthreads();

#pragma unroll
        for (int kb = 0; kb < 3; kb++) {
            uint32_t a[2][4], b[4][4];
#pragma unroll
            for (int f = 0; f < 2; f++) ldsm4(a[f], aaddr[f] + kb * 32);
#pragma unroll
            for (int p = 0; p < 4; p++) ldsm4(b[p], baddr[p] + kb * 32);
#pragma unroll
            for (int f = 0; f < 2; f++)
#pragma unroll
                for (int p = 0; p < 4; p++) {
                    mma16816(acc[f][2 * p],     a[f], b[p][0], b[p][1]);
                    mma16816(acc[f][2 * p + 1], a[f], b[p][2], b[p][3]);
                }
        }
        __syncthreads();
    }

#pragma unroll
    for (int f = 0; f < 2; f++) {
#pragma unroll
        for (int nf = 0; nf < 8; nf++) {
            int col = n0 + n_base + nf * 8 + 2 * (lane & 3);
            float2 bv = *(const float2*)&bias[col];
            int row = m0 + m_base + f * 16 + (lane >> 2);
            if (row < M) {
                float2 o;
                o.x = fmaxf(acc[f][nf][0] + bv.x, 0.0f);
                o.y = fmaxf(acc[f][nf][1] + bv.y, 0.0f);
                *(float2*)(C + (size_t)row * Nc + col) = o;
            }
            int row2 = row + 8;
            if (row2 < M) {
                float2 o;
                o.x = fmaxf(acc[f][nf][2] + bv.x, 0.0f);
                o.y = fmaxf(acc[f][nf][3] + bv.y, 0.0f);
                *(float2*)(C + (size_t)row2 * Nc + col) = o;
            }
        }
    }
}

// out[i] = sigmoid(dot(h[i,:256], Wf) + bf) ; one warp per node
__global__ void final_kernel(const float* __restrict__ Hin,
                             const float* __restrict__ Wf,
                             const float* __restrict__ bf,
                             float* __restrict__ out) {
    int gwarp = (blockIdx.x * blockDim.x + threadIdx.x) >> 5;
    int lane = threadIdx.x & 31;
    if (gwarp >= Nn) return;
    float v = 0.0f;
#pragma unroll
    for (int tc = 0; tc < 8; tc++)
        v = fmaf(Hin[(size_t)gwarp * Hh + lane + tc * 32], Wf[lane + tc * 32], v);
#pragma unroll
    for (int off = 16; off > 0; off >>= 1)
        v += __shfl_xor_sync(FULLM, v, off);
    if (lane == 0) {
        float z = v + bf[0];
        out[gwarp] = 1.0f / (1.0f + expf(-z));
    }
}

// ---------------- host launcher --------------------
extern "C" void kernel_launch(void* const* d_in, const int* in_sizes, int n_in,
                              void* d_out, int out_size) {
    const float* x       = (const float*)d_in[0];
    const float* centers = (const float*)d_in[1];
    const float* W0      = (const float*)d_in[2];
    const float* b0      = (const float*)d_in[3];
    const float* W1      = (const float*)d_in[4];
    const float* b1      = (const float*)d_in[5];
    const float* W2      = (const float*)d_in[6];
    const float* b2      = (const float*)d_in[7];
    const float* Wf      = (const float*)d_in[8];
    const float* bf      = (const float*)d_in[9];
    float* out = (float*)d_out;
    (void)in_sizes; (void)n_in; (void)out_size;

    void *pH, *pS, *pW, *pCnt, *pDeg;
    cudaGetSymbolAddress(&pH, g_bufH);
    cudaGetSymbolAddress(&pS, g_bufS);
    cudaGetSymbolAddress(&pW, g_wt2);
    cudaGetSymbolAddress(&pCnt, g_cellCnt);
    cudaGetSymbolAddress(&pDeg, g_deg);
    float*    Hbuf = (float*)pH;
    uint32_t* Sbuf = (uint32_t*)pS;
    uint32_t* Wbuf = (uint32_t*)pW;

    cudaMemsetAsync(pCnt, 0, NC * sizeof(int));
    cudaMemsetAsync(pDeg, 0, Nn * sizeof(int));
    assign_kernel<<<(Nn + 255) / 256, 256>>>(centers);
    scan_kernel<<<1, 1024>>>();
    scatter_kernel<<<(Nn + 255) / 256, 256>>>(centers);
    knn_kernel<<<(Nn * 32 + 255) / 256, 256>>>();
    deg_kernel<<<(Nn * Kk + 255) / 256, 256>>>();
    srcn_kernel<<<(Nn + 255) / 256, 256>>>();

    dim3 ggrid(Hh / BN, (Nn + BM - 1) / BM);

    // layer 0  (F=128: 8 nodes/block)
    aggregate_kernel<Dd><<<(Nn + 7) / 8, 256>>>(x, Sbuf);
    convw_kernel<<<(Dd * Hh + 255) / 256, 256>>>(W0, Dd);
    mma_gemm_kernel<<<ggrid, 256>>>(Sbuf, Wbuf, b0, Hbuf, Nn, Dd, Hh);

    // layer 1  (F=256: 4 nodes/block)
    aggregate_kernel<Hh><<<(Nn + 3) / 4, 256>>>(Hbuf, Sbuf);
    convw_kernel<<<(Hh * Hh + 255) / 256, 256>>>(W1, Hh);
    mma_gemm_kernel<<<ggrid, 256>>>(Sbuf, Wbuf, b1, Hbuf, Nn, Hh, Hh);

    // layer 2
    aggregate_kernel<Hh><<<(Nn + 3) / 4, 256>>>(Hbuf, Sbuf);
    convw_kernel<<<(Hh * Hh + 255) / 256, 256>>>(W2, Hh);
    mma_gemm_kernel<<<ggrid, 256>>>(Sbuf, Wbuf, b2, Hbuf, Nn, Hh, Hh);

    // final
    final_kernel<<<(Nn * 32 + 255) / 256, 256>>>(Hbuf, Wf, bf, out);
}

// round 7
// speedup vs baseline: 1.0785x; 1.0785x over previous
#include <cuda_runtime.h>
#include <cuda_bf16.h>
#include <math.h>
#include <stdint.h>

// ---------------- problem constants ----------------
#define Nn 20000
#define Dd 128
#define Hh 256
#define Kk 16

// ---------------- grid constants -------------------
#define GG 24
#define NC (GG * GG * GG)        // 13824
#define XMIN (-6.0f)
#define CELL (0.5f)
#define INV_CELL (2.0f)
#define FINF 3.4e38f
#define FULLM 0xffffffffu

// ---------------- scratch (static device) ----------
__device__ int   g_cellOf[Nn];
__device__ int   g_cellCnt[NC];
__device__ int   g_cellStart[NC + 1];
__device__ int   g_cellCur[NC];
__device__ float4 g_pts[Nn];      // (x, y, z, sq) sorted by cell
__device__ int   g_ptIdx[Nn];     // original index, sorted by cell
__device__ int   g_knn[Nn * Kk];
__device__ int   g_deg[Nn];
__device__ float g_srcn[Nn];
__device__ __align__(16) float    g_bufH[Nn * Hh];
__device__ __align__(16) uint32_t g_bufS[Nn * Hh];
__device__ __align__(16) uint32_t g_wt2[Hh * Hh];

// ---------------- small helpers --------------------
__device__ __forceinline__ int cellc(float v) {
    int c = (int)floorf((v - XMIN) * INV_CELL);
    return min(max(c, 0), GG - 1);
}

__device__ __forceinline__ uint32_t pack_split(float v) {
    __nv_bfloat16 h = __float2bfloat16(v);
    float hf = __bfloat162float(h);
    __nv_bfloat16 l = __float2bfloat16(v - hf);
    unsigned short hs = *reinterpret_cast<unsigned short*>(&h);
    unsigned short ls = *reinterpret_cast<unsigned short*>(&l);
    return (uint32_t)hs | ((uint32_t)ls << 16);
}

__device__ __forceinline__ uint32_t smem_u32(const void* p) {
    uint32_t a;
    asm("{ .reg .u64 t; cvta.to.shared.u64 t, %1; cvt.u32.u64 %0, t; }"
        : "=r"(a) : "l"(p));
    return a;
}

__device__ __forceinline__ void ldsm4(uint32_t* r, uint32_t addr) {
    asm volatile("ldmatrix.sync.aligned.m8n8.x4.shared.b16 {%0,%1,%2,%3}, [%4];"
                 : "=r"(r[0]), "=r"(r[1]), "=r"(r[2]), "=r"(r[3]) : "r"(addr));
}

__device__ __forceinline__ void mma16816(float* c, const uint32_t* a,
                                         const uint32_t b0, const uint32_t b1) {
    asm volatile(
        "mma.sync.aligned.m16n8k16.row.col.f32.bf16.bf16.f32 "
        "{%0,%1,%2,%3}, {%4,%5,%6,%7}, {%8,%9}, {%0,%1,%2,%3};"
        : "+f"(c[0]), "+f"(c[1]), "+f"(c[2]), "+f"(c[3])
        : "r"(a[0]), "r"(a[1]), "r"(a[2]), "r"(a[3]), "r"(b0), "r"(b1));
}

// ---------------- setup kernels --------------------

__global__ void assign_kernel(const float* __restrict__ centers) {
    int i = blockIdx.x * blockDim.x + threadIdx.x;
    if (i >= Nn) return;
    float x = centers[3 * i], y = centers[3 * i + 1], z = centers[3 * i + 2];
    int cid = (cellc(z) * GG + cellc(y)) * GG + cellc(x);
    g_cellOf[i] = cid;
    atomicAdd(&g_cellCnt[cid], 1);
}

__global__ void scan_kernel() {
    const int per = 14;   // 1024*14 = 14336 >= NC
    int t = threadIdx.x;
    int base = t * per;
    int s = 0;
    for (int i = 0; i < per; i++) {
        int idx = base + i;
        s += (idx < NC) ? g_cellCnt[idx] : 0;
    }

    int lane = t & 31, w = t >> 5;
    int v = s;
    for (int o = 1; o < 32; o <<= 1) {
        int n = __shfl_up_sync(FULLM, v, o);
        if (lane >= o) v += n;
    }
    __shared__ int ws[32];
    if (lane == 31) ws[w] = v;
    __syncthreads();
    if (w == 0) {
        int xv = ws[lane];
        for (int o = 1; o < 32; o <<= 1) {
            int n = __shfl_up_sync(FULLM, xv, o);
            if (lane >= o) xv += n;
        }
        ws[lane] = xv;
    }
    __syncthreads();
    int excl = v - s + (w ? ws[w - 1] : 0);
    int run = excl;
    for (int i = 0; i < per; i++) {
        int idx = base + i;
        if (idx < NC) {
            int c = g_cellCnt[idx];
            g_cellStart[idx] = run;
            g_cellCur[idx] = run;
            run += c;
        }
    }
    if (t == 1023) g_cellStart[NC] = Nn;
}

__global__ void scatter_kernel(const float* __restrict__ centers) {
    int i = blockIdx.x * blockDim.x + threadIdx.x;
    if (i >= Nn) return;
    int cid = g_cellOf[i];
    int pos = atomicAdd(&g_cellCur[cid], 1);
    float x = centers[3 * i], y = centers[3 * i + 1], z = centers[3 * i + 2];
    float sq = fmaf(z, z, fmaf(y, y, x * x));
    g_pts[pos] = make_float4(x, y, z, sq);
    g_ptIdx[pos] = i;
}

// ---------------- warp-per-query exact kNN (Round-5 proven version) ----------
// Warp-distributed sorted top-16: lane j holds j-th best (d2, idx), ascending.
__global__ void __launch_bounds__(256) knn_kernel() {
    int gw = (blockIdx.x * blockDim.x + threadIdx.x) >> 5;
    int lane = threadIdx.x & 31;
    if (gw >= Nn) return;
    float4 q = g_pts[gw];
    int orig = g_ptIdx[gw];
    float qx = q.x, qy = q.y, qz = q.z, qsq = q.w;
    int cx = cellc(qx), cy = cellc(qy), cz = cellc(qz);

    float ld = FINF;   // distributed list: lane j = j-th smallest d2
    int   li = 0;
    float gth = FINF;  // current 16th-best (uniform)

    int Rcov = max(max(max(cx, GG - 1 - cx), max(cy, GG - 1 - cy)),
                   max(cz, GG - 1 - cz));

    for (int R = 0; R <= Rcov; R++) {
        int zlo = max(cz - R, 0), zhi = min(cz + R, GG - 1);
        int ylo = max(cy - R, 0), yhi = min(cy + R, GG - 1);
        int xlo = max(cx - R, 0), xhi = min(cx + R, GG - 1);
        for (int z = zlo; z <= zhi; z++) {
            int adz = abs(z - cz);
            for (int y = ylo; y <= yhi; y++) {
                int dzy = max(adz, abs(y - cy));
                int runs[2][2];
                int nruns = 0;
                if (dzy == R) {
                    runs[0][0] = xlo; runs[0][1] = xhi; nruns = 1;
                } else {
                    if (cx - R >= 0) { runs[nruns][0] = cx - R; runs[nruns][1] = cx - R; nruns++; }
                    if (cx + R < GG) { runs[nruns][0] = cx + R; runs[nruns][1] = cx + R; nruns++; }
                }
                int rowbase = (z * GG + y) * GG;
                for (int r = 0; r < nruns; r++) {
                    int p0 = g_cellStart[rowbase + runs[r][0]];
                    int p1 = g_cellStart[rowbase + runs[r][1] + 1];
                    for (int pb = p0; pb < p1; pb += 32) {
                        int p = pb + lane;
                        float d2 = FINF;
                        int pid = 0;
                        if (p < p1) {
                            float4 c = g_pts[p];
                            float t1 = fmaf(qx, c.x, fmaf(qy, c.y, qz * c.z));
                            d2 = fmaf(-2.0f, t1, qsq + c.w);
                            pid = g_ptIdx[p];
                        }
                        unsigned mask = __ballot_sync(FULLM, d2 < gth);
                        while (mask) {
                            int src = __ffs(mask) - 1;
                            mask &= mask - 1;
                            float nd = __shfl_sync(FULLM, d2, src);
                            int   ni = __shfl_sync(FULLM, pid, src);
                            if (nd >= gth) continue;           // uniform
                            unsigned le = __ballot_sync(FULLM, ld <= nd);
                            int pos = __popc(le);
                            float pd = __shfl_up_sync(FULLM, ld, 1);
                            int   pi = __shfl_up_sync(FULLM, li, 1);
                            if (lane >= pos) { ld = pd; li = pi; }
                            if (lane == pos) { ld = nd; li = ni; }
                            gth = __shfl_sync(FULLM, ld, 15);
                        }
                    }
                }
            }
        }
        // stopping rule: gth is exact 16th best so far (uniform)
        if (gth < FINF) {
            float bx = fminf(qx - (XMIN + (float)(cx - R) * CELL),
                             (XMIN + (float)(cx + R + 1) * CELL) - qx);
            float by = fminf(qy - (XMIN + (float)(cy - R) * CELL),
                             (XMIN + (float)(cy + R + 1) * CELL) - qy);
            float bz = fminf(qz - (XMIN + (float)(cz - R) * CELL),
                             (XMIN + (float)(cz + R + 1) * CELL) - qz);
            float b = fmaxf(fminf(bx, fminf(by, bz)), 0.0f);
            if (gth <= b * b) break;
        }
    }

    if (lane < Kk) g_knn[orig * Kk + lane] = li;
}

__global__ void deg_kernel() {
    int e = blockIdx.x * blockDim.x + threadIdx.x;
    if (e < Nn * Kk) atomicAdd(&g_deg[g_knn[e]], 1);
}

__global__ void srcn_kernel() {
    int i = blockIdx.x * blockDim.x + threadIdx.x;
    if (i < Nn) g_srcn[i] = rsqrtf(fmaxf((float)g_deg[i], 1.0f));
}

// split-transpose of W[k][Hh] -> Wt2[n][Kd] packed (hi | lo<<16)
__global__ void convw_kernel(const float* __restrict__ W, int Kd) {
    int i = blockIdx.x * blockDim.x + threadIdx.x;
    if (i >= Kd * Hh) return;
    int k = i % Kd;
    int n = i / Kd;
    g_wt2[(size_t)n * Kd + k] = pack_split(W[(size_t)k * Hh + n]);
}

// agg[i, :] = 0.25 * sum_k h[knn[i,k], :] * srcn[knn[i,k]]  -> packed split
// float4 vectorized; TPN = F/4 threads per node, 256-thread blocks.
template <int F>
__global__ void __launch_bounds__(256) aggregate_kernel(
    const float* __restrict__ Hin, uint32_t* __restrict__ Sout) {
    const int TPN = F / 4;
    const int NPB = 256 / TPN;
    __shared__ int   jj[NPB][Kk];
    __shared__ float ss[NPB][Kk];
    int g = threadIdx.x / TPN;
    int t = threadIdx.x % TPN;
    int node = blockIdx.x * NPB + g;
    bool ok = node < Nn;
    if (ok && t < Kk) {
        int j = g_knn[node * Kk + t];
        jj[g][t] = j;
        ss[g][t] = g_srcn[j];
    }
    __syncthreads();
    if (!ok) return;
    float4 acc = make_float4(0.f, 0.f, 0.f, 0.f);
#pragma unroll
    for (int k = 0; k < Kk; k++) {
        const float4* row = (const float4*)(Hin + (size_t)jj[g][k] * F);
        float4 v = row[t];
        float s = ss[g][k];
        acc.x = fmaf(v.x, s, acc.x);
        acc.y = fmaf(v.y, s, acc.y);
        acc.z = fmaf(v.z, s, acc.z);
        acc.w = fmaf(v.w, s, acc.w);
    }
    uint4 o;
    o.x = pack_split(acc.x * 0.25f);
    o.y = pack_split(acc.y * 0.25f);
    o.z = pack_split(acc.z * 0.25f);
    o.w = pack_split(acc.w * 0.25f);
    *(uint4*)(Sout + (size_t)node * F + t * 4) = o;
}

// ---------------- tensor-core GEMM -----------------
#define BM 128
#define BN 128
#define BK 16
#define LDA 56

__global__ void __launch_bounds__(256, 2) mma_gemm_kernel(
    const uint32_t* __restrict__ A2, const uint32_t* __restrict__ B2,
    const float* __restrict__ bias, float* __restrict__ C,
    int M, int Kd, int Nc) {
    __shared__ __align__(16) uint16_t As[BM * LDA];
    __shared__ __align__(16) uint16_t Bs[BN * LDA];

    int t = threadIdx.x;
    int lane = t & 31;
    int wid = t >> 5;
    int m0 = blockIdx.y * BM;
    int n0 = blockIdx.x * BN;

    int wm = wid & 3;
    int wn = wid >> 2;
    int m_base = wm * 32;
    int n_base = wn * 64;

    uint32_t as_base = smem_u32(As);
    uint32_t bs_base = smem_u32(Bs);

    uint32_t aaddr[2], baddr[4];
#pragma unroll
    for (int f = 0; f < 2; f++) {
        int row = m_base + f * 16 + (lane & 7) + (lane & 8);
        int koff = (lane & 16) ? 16 : 0;
        aaddr[f] = as_base + row * (LDA * 2) + koff;
    }
#pragma unroll
    for (int p = 0; p < 4; p++) {
        int row = n_base + p * 16 + (lane & 7) + ((lane & 16) >> 1);
        int koff = (lane & 8) ? 16 : 0;
        baddr[p] = bs_base + row * (LDA * 2) + koff;
    }

    float acc[2][8][4];
#pragma unroll
    for (int f = 0; f < 2; f++)
#pragma unroll
        for (int nf = 0; nf < 8; nf++)
#pragma unroll
            for (int c = 0; c < 4; c++) acc[f][nf][c] = 0.0f;

    uint32_t* As32 = (uint32_t*)As;
    uint32_t* Bs32 = (uint32_t*)Bs;

    const int steps = Kd / BK;
    for (int s = 0; s < steps; s++) {
        int k0 = s * BK;
#pragma unroll
        for (int v = 0; v < 2; v++) {
            int vec = t + v * 256;
            int row = vec >> 2, q = vec & 3;
            int gm = m0 + row;
            uint4 d = make_uint4(0u, 0u, 0u, 0u);
            if (gm < M)
                d = *(const uint4*)(A2 + (size_t)gm * Kd + k0 + q * 4);
            uint32_t h0 = d.x & 0xffffu, l0 = d.x >> 16;
            uint32_t h1 = d.y & 0xffffu, l1 = d.y >> 16;
            uint32_t h2 = d.z & 0xffffu, l2 = d.z >> 16;
            uint32_t h3 = d.w & 0xffffu, l3 = d.w >> 16;
            uint32_t hp0 = h0 | (h1 << 16), hp1 = h2 | (h3 << 16);
            uint32_t lp0 = l0 | (l1 << 16), lp1 = l2 | (l3 << 16);
            int b32 = row * (LDA / 2) + 2 * q;
            As32[b32 + 0] = hp0;  As32[b32 + 1] = hp1;
            As32[b32 + 8] = lp0;  As32[b32 + 9] = lp1;
            As32[b32 + 16] = hp0; As32[b32 + 17] = hp1;
        }
#pragma unroll
        for (int v = 0; v < 2; v++) {
            int vec = t + v * 256;
            int row = vec >> 2, q = vec & 3;
            uint4 d = *(const uint4*)(B2 + (size_t)(n0 + row) * Kd + k0 + q * 4);
            uint32_t h0 = d.x & 0xffffu, l0 = d.x >> 16;
            uint32_t h1 = d.y & 0xffffu, l1 = d.y >> 16;
            uint32_t h2 = d.z & 0xffffu, l2 = d.z >> 16;
            uint32_t h3 = d.w & 0xffffu, l3 = d.w >> 16;
            uint32_t hp0 = h0 | (h1 << 16), hp1 = h2 | (h3 << 16);
            uint32_t lp0 = l0 | (l1 << 16), lp1 = l2 | (l3 << 16);
            int b32 = row * (LDA / 2) + 2 * q;
            Bs32[b32 + 0] = hp0;  Bs32[b32 + 1] = hp1;
            Bs32[b32 + 8] = hp0;  Bs32[b32 + 9] = hp1;
            Bs32[b32 + 16] = lp0; Bs32[b32 + 17] = lp1;
        }
        __syncthreads();

#pragma unroll
        for (int kb = 0; kb < 3; kb++) {
            uint32_t a[2][4], b[4][4];
#pragma unroll
            for (int f = 0; f < 2; f++) ldsm4(a[f], aaddr[f] + kb * 32);
#pragma unroll
            for (int p = 0; p < 4; p++) ldsm4(b[p], baddr[p] + kb * 32);
#pragma unroll
            for (int f = 0; f < 2; f++)
#pragma unroll
                for (int p = 0; p < 4; p++) {
                    mma16816(acc[f][2 * p],     a[f], b[p][0], b[p][1]);
                    mma16816(acc[f][2 * p + 1], a[f], b[p][2], b[p][3]);
                }
        }
        __syncthreads();
    }

#pragma unroll
    for (int f = 0; f < 2; f++) {
#pragma unroll
        for (int nf = 0; nf < 8; nf++) {
            int col = n0 + n_base + nf * 8 + 2 * (lane & 3);
            float2 bv = *(const float2*)&bias[col];
            int row = m0 + m_base + f * 16 + (lane >> 2);
            if (row < M) {
                float2 o;
                o.x = fmaxf(acc[f][nf][0] + bv.x, 0.0f);
                o.y = fmaxf(acc[f][nf][1] + bv.y, 0.0f);
                *(float2*)(C + (size_t)row * Nc + col) = o;
            }
            int row2 = row + 8;
            if (row2 < M) {
                float2 o;
                o.x = fmaxf(acc[f][nf][2] + bv.x, 0.0f);
                o.y = fmaxf(acc[f][nf][3] + bv.y, 0.0f);
                *(float2*)(C + (size_t)row2 * Nc + col) = o;
            }
        }
    }
}

// out[i] = sigmoid(dot(h[i,:256], Wf) + bf) ; one warp per node
__global__ void final_kernel(const float* __restrict__ Hin,
                             const float* __restrict__ Wf,
                             const float* __restrict__ bf,
                             float* __restrict__ out) {
    int gwarp = (blockIdx.x * blockDim.x + threadIdx.x) >> 5;
    int lane = threadIdx.x & 31;
    if (gwarp >= Nn) return;
    float v = 0.0f;
#pragma unroll
    for (int tc = 0; tc < 8; tc++)
        v = fmaf(Hin[(size_t)gwarp * Hh + lane + tc * 32], Wf[lane + tc * 32], v);
#pragma unroll
    for (int off = 16; off > 0; off >>= 1)
        v += __shfl_xor_sync(FULLM, v, off);
    if (lane == 0) {
        float z = v + bf[0];
        out[gwarp] = 1.0f / (1.0f + expf(-z));
    }
}

// ---------------- host launcher --------------------
extern "C" void kernel_launch(void* const* d_in, const int* in_sizes, int n_in,
                              void* d_out, int out_size) {
    const float* x       = (const float*)d_in[0];
    const float* centers = (const float*)d_in[1];
    const float* W0      = (const float*)d_in[2];
    const float* b0      = (const float*)d_in[3];
    const float* W1      = (const float*)d_in[4];
    const float* b1      = (const float*)d_in[5];
    const float* W2      = (const float*)d_in[6];
    const float* b2      = (const float*)d_in[7];
    const float* Wf      = (const float*)d_in[8];
    const float* bf      = (const float*)d_in[9];
    float* out = (float*)d_out;
    (void)in_sizes; (void)n_in; (void)out_size;

    void *pH, *pS, *pW, *pCnt, *pDeg;
    cudaGetSymbolAddress(&pH, g_bufH);
    cudaGetSymbolAddress(&pS, g_bufS);
    cudaGetSymbolAddress(&pW, g_wt2);
    cudaGetSymbolAddress(&pCnt, g_cellCnt);
    cudaGetSymbolAddress(&pDeg, g_deg);
    float*    Hbuf = (float*)pH;
    uint32_t* Sbuf = (uint32_t*)pS;
    uint32_t* Wbuf = (uint32_t*)pW;

    cudaMemsetAsync(pCnt, 0, NC * sizeof(int));
    cudaMemsetAsync(pDeg, 0, Nn * sizeof(int));
    assign_kernel<<<(Nn + 255) / 256, 256>>>(centers);
    scan_kernel<<<1, 1024>>>();
    scatter_kernel<<<(Nn + 255) / 256, 256>>>(centers);
    knn_kernel<<<(Nn * 32 + 255) / 256, 256>>>();
    deg_kernel<<<(Nn * Kk + 255) / 256, 256>>>();
    srcn_kernel<<<(Nn + 255) / 256, 256>>>();

    dim3 ggrid(Hh / BN, (Nn + BM - 1) / BM);

    // layer 0  (F=128: 8 nodes/block)
    aggregate_kernel<Dd><<<(Nn + 7) / 8, 256>>>(x, Sbuf);
    convw_kernel<<<(Dd * Hh + 255) / 256, 256>>>(W0, Dd);
    mma_gemm_kernel<<<ggrid, 256>>>(Sbuf, Wbuf, b0, Hbuf, Nn, Dd, Hh);

    // layer 1  (F=256: 4 nodes/block)
    aggregate_kernel<Hh><<<(Nn + 3) / 4, 256>>>(Hbuf, Sbuf);
    convw_kernel<<<(Hh * Hh + 255) / 256, 256>>>(W1, Hh);
    mma_gemm_kernel<<<ggrid, 256>>>(Sbuf, Wbuf, b1, Hbuf, Nn, Hh, Hh);

    // layer 2
    aggregate_kernel<Hh><<<(Nn + 3) / 4, 256>>>(Hbuf, Sbuf);
    convw_kernel<<<(Hh * Hh + 255) / 256, 256>>>(W2, Hh);
    mma_gemm_kernel<<<ggrid, 256>>>(Sbuf, Wbuf, b2, Hbuf, Nn, Hh, Hh);

    // final
    final_kernel<<<(Nn * 32 + 255) / 256, 256>>>(Hbuf, Wf, bf, out);
}

// round 8
// speedup vs baseline: 1.1304x; 1.0481x over previous
#include <cuda_runtime.h>
#include <cuda_bf16.h>
#include <math.h>
#include <stdint.h>

// ---------------- problem constants ----------------
#define Nn 20000
#define Dd 128
#define Hh 256
#define Kk 16

// ---------------- grid constants -------------------
#define GG 24
#define NC (GG * GG * GG)        // 13824
#define XMIN (-6.0f)
#define CELL (0.5f)
#define INV_CELL (2.0f)
#define FINF 3.4e38f
#define FULLM 0xffffffffu

// ---------------- scratch (static device) ----------
__device__ int   g_cellOf[Nn];
__device__ int   g_cellCnt[NC];
__device__ int   g_cellStart[NC + 1];
__device__ int   g_cellCur[NC];
__device__ float4 g_pts[Nn];      // (x, y, z, sq) sorted by cell
__device__ int   g_ptIdx[Nn];     // original index, sorted by cell
__device__ int   g_knn[Nn * Kk];
__device__ int   g_deg[Nn];
__device__ float g_srcn[Nn];
__device__ __align__(16) float    g_bufH[Nn * Hh];
__device__ __align__(16) uint32_t g_bufS[Nn * Hh];
__device__ __align__(16) uint32_t g_w0s[Dd * Hh];   // packed split W0^T [n][k]
__device__ __align__(16) uint32_t g_w1s[Hh * Hh];   // packed split W1^T
__device__ __align__(16) uint32_t g_w2s[Hh * Hh];   // packed split W2^T

// ---------------- small helpers --------------------
__device__ __forceinline__ int cellc(float v) {
    int c = (int)floorf((v - XMIN) * INV_CELL);
    return min(max(c, 0), GG - 1);
}

__device__ __forceinline__ uint32_t pack_split(float v) {
    __nv_bfloat16 h = __float2bfloat16(v);
    float hf = __bfloat162float(h);
    __nv_bfloat16 l = __float2bfloat16(v - hf);
    unsigned short hs = *reinterpret_cast<unsigned short*>(&h);
    unsigned short ls = *reinterpret_cast<unsigned short*>(&l);
    return (uint32_t)hs | ((uint32_t)ls << 16);
}

__device__ __forceinline__ uint32_t smem_u32(const void* p) {
    uint32_t a;
    asm("{ .reg .u64 t; cvta.to.shared.u64 t, %1; cvt.u32.u64 %0, t; }"
        : "=r"(a) : "l"(p));
    return a;
}

__device__ __forceinline__ void ldsm4(uint32_t* r, uint32_t addr) {
    asm volatile("ldmatrix.sync.aligned.m8n8.x4.shared.b16 {%0,%1,%2,%3}, [%4];"
                 : "=r"(r[0]), "=r"(r[1]), "=r"(r[2]), "=r"(r[3]) : "r"(addr));
}

__device__ __forceinline__ void mma16816(float* c, const uint32_t* a,
                                         const uint32_t b0, const uint32_t b1) {
    asm volatile(
        "mma.sync.aligned.m16n8k16.row.col.f32.bf16.bf16.f32 "
        "{%0,%1,%2,%3}, {%4,%5,%6,%7}, {%8,%9}, {%0,%1,%2,%3};"
        : "+f"(c[0]), "+f"(c[1]), "+f"(c[2]), "+f"(c[3])
        : "r"(a[0]), "r"(a[1]), "r"(a[2]), "r"(a[3]), "r"(b0), "r"(b1));
}

// ---------------- setup kernels --------------------

__global__ void assign_kernel(const float* __restrict__ centers) {
    int i = blockIdx.x * blockDim.x + threadIdx.x;
    if (i >= Nn) return;
    float x = centers[3 * i], y = centers[3 * i + 1], z = centers[3 * i + 2];
    int cid = (cellc(z) * GG + cellc(y)) * GG + cellc(x);
    g_cellOf[i] = cid;
    atomicAdd(&g_cellCnt[cid], 1);
}

__global__ void scan_kernel() {
    const int per = 14;   // 1024*14 = 14336 >= NC
    int t = threadIdx.x;
    int base = t * per;
    int s = 0;
    for (int i = 0; i < per; i++) {
        int idx = base + i;
        s += (idx < NC) ? g_cellCnt[idx] : 0;
    }

    int lane = t & 31, w = t >> 5;
    int v = s;
    for (int o = 1; o < 32; o <<= 1) {
        int n = __shfl_up_sync(FULLM, v, o);
        if (lane >= o) v += n;
    }
    __shared__ int ws[32];
    if (lane == 31) ws[w] = v;
    __syncthreads();
    if (w == 0) {
        int xv = ws[lane];
        for (int o = 1; o < 32; o <<= 1) {
            int n = __shfl_up_sync(FULLM, xv, o);
            if (lane >= o) xv += n;
        }
        ws[lane] = xv;
    }
    __syncthreads();
    int excl = v - s + (w ? ws[w - 1] : 0);
    int run = excl;
    for (int i = 0; i < per; i++) {
        int idx = base + i;
        if (idx < NC) {
            int c = g_cellCnt[idx];
            g_cellStart[idx] = run;
            g_cellCur[idx] = run;
            run += c;
        }
    }
    if (t == 1023) g_cellStart[NC] = Nn;
}

__global__ void scatter_kernel(const float* __restrict__ centers) {
    int i = blockIdx.x * blockDim.x + threadIdx.x;
    if (i >= Nn) return;
    int cid = g_cellOf[i];
    int pos = atomicAdd(&g_cellCur[cid], 1);
    float x = centers[3 * i], y = centers[3 * i + 1], z = centers[3 * i + 2];
    float sq = fmaf(z, z, fmaf(y, y, x * x));
    g_pts[pos] = make_float4(x, y, z, sq);
    g_ptIdx[pos] = i;
}

// ---------------- warp-per-query exact kNN ----------------
__global__ void __launch_bounds__(256) knn_kernel() {
    int gw = (blockIdx.x * blockDim.x + threadIdx.x) >> 5;
    int lane = threadIdx.x & 31;
    if (gw >= Nn) return;
    float4 q = g_pts[gw];
    int orig = g_ptIdx[gw];
    float qx = q.x, qy = q.y, qz = q.z, qsq = q.w;
    int cx = cellc(qx), cy = cellc(qy), cz = cellc(qz);

    float ld = FINF;   // distributed list: lane j = j-th smallest d2
    int   li = 0;
    float gth = FINF;  // current 16th-best (uniform)

    int Rcov = max(max(max(cx, GG - 1 - cx), max(cy, GG - 1 - cy)),
                   max(cz, GG - 1 - cz));

    for (int R = 0; R <= Rcov; R++) {
        int zlo = max(cz - R, 0), zhi = min(cz + R, GG - 1);
        int ylo = max(cy - R, 0), yhi = min(cy + R, GG - 1);
        int xlo = max(cx - R, 0), xhi = min(cx + R, GG - 1);
        for (int z = zlo; z <= zhi; z++) {
            int adz = abs(z - cz);
            for (int y = ylo; y <= yhi; y++) {
                int dzy = max(adz, abs(y - cy));
                int runs[2][2];
                int nruns = 0;
                if (dzy == R) {
                    runs[0][0] = xlo; runs[0][1] = xhi; nruns = 1;
                } else {
                    if (cx - R >= 0) { runs[nruns][0] = cx - R; runs[nruns][1] = cx - R; nruns++; }
                    if (cx + R < GG) { runs[nruns][0] = cx + R; runs[nruns][1] = cx + R; nruns++; }
                }
                int rowbase = (z * GG + y) * GG;
                for (int r = 0; r < nruns; r++) {
                    int p0 = g_cellStart[rowbase + runs[r][0]];
                    int p1 = g_cellStart[rowbase + runs[r][1] + 1];
                    for (int pb = p0; pb < p1; pb += 32) {
                        int p = pb + lane;
                        float d2 = FINF;
                        int pid = 0;
                        if (p < p1) {
                            float4 c = g_pts[p];
                            float t1 = fmaf(qx, c.x, fmaf(qy, c.y, qz * c.z));
                            d2 = fmaf(-2.0f, t1, qsq + c.w);
                            pid = g_ptIdx[p];
                        }
                        unsigned mask = __ballot_sync(FULLM, d2 < gth);
                        while (mask) {
                            int src = __ffs(mask) - 1;
                            mask &= mask - 1;
                            float nd = __shfl_sync(FULLM, d2, src);
                            int   ni = __shfl_sync(FULLM, pid, src);
                            if (nd >= gth) continue;           // uniform
                            unsigned le = __ballot_sync(FULLM, ld <= nd);
                            int pos = __popc(le);
                            float pd = __shfl_up_sync(FULLM, ld, 1);
                            int   pi = __shfl_up_sync(FULLM, li, 1);
                            if (lane >= pos) { ld = pd; li = pi; }
                            if (lane == pos) { ld = nd; li = ni; }
                            gth = __shfl_sync(FULLM, ld, 15);
                        }
                    }
                }
            }
        }
        if (gth < FINF) {
            float bx = fminf(qx - (XMIN + (float)(cx - R) * CELL),
                             (XMIN + (float)(cx + R + 1) * CELL) - qx);
            float by = fminf(qy - (XMIN + (float)(cy - R) * CELL),
                             (XMIN + (float)(cy + R + 1) * CELL) - qy);
            float bz = fminf(qz - (XMIN + (float)(cz - R) * CELL),
                             (XMIN + (float)(cz + R + 1) * CELL) - qz);
            float b = fmaxf(fminf(bx, fminf(by, bz)), 0.0f);
            if (gth <= b * b) break;
        }
    }

    if (lane < Kk) g_knn[orig * Kk + lane] = li;
}

__global__ void deg_kernel() {
    int e = blockIdx.x * blockDim.x + threadIdx.x;
    if (e < Nn * Kk) atomicAdd(&g_deg[g_knn[e]], 1);
}

__global__ void srcn_kernel() {
    int i = blockIdx.x * blockDim.x + threadIdx.x;
    if (i < Nn) g_srcn[i] = rsqrtf(fmaxf((float)g_deg[i], 1.0f));
}

// split-transpose of all three weight matrices in one launch
__global__ void convw_all_kernel(const float* __restrict__ W0,
                                 const float* __restrict__ W1,
                                 const float* __restrict__ W2) {
    int i = blockIdx.x * blockDim.x + threadIdx.x;
    if (i < Dd * Hh) {
        int k = i % Dd, n = i / Dd;
        g_w0s[(size_t)n * Dd + k] = pack_split(W0[(size_t)k * Hh + n]);
    }
    if (i < Hh * Hh) {
        int k = i % Hh, n = i / Hh;
        g_w1s[(size_t)n * Hh + k] = pack_split(W1[(size_t)k * Hh + n]);
        g_w2s[(size_t)n * Hh + k] = pack_split(W2[(size_t)k * Hh + n]);
    }
}

// agg[node, :] = 0.25 * sum_k h[knn[node,k], :] * srcn[knn[node,k]]  -> packed split
// Nodes processed in CELL-SORTED order (g_ptIdx) so co-scheduled nodes share
// neighbors and the gathers hit L1.
template <int F>
__global__ void __launch_bounds__(256) aggregate_kernel(
    const float* __restrict__ Hin, uint32_t* __restrict__ Sout) {
    const int TPN = F / 4;
    const int NPB = 256 / TPN;
    __shared__ int   jj[NPB][Kk];
    __shared__ float ss[NPB][Kk];
    int g = threadIdx.x / TPN;
    int t = threadIdx.x % TPN;
    int pos = blockIdx.x * NPB + g;
    bool ok = pos < Nn;
    int node = 0;
    if (ok) {
        node = g_ptIdx[pos];
        if (t < Kk) {
            int j = g_knn[node * Kk + t];
            jj[g][t] = j;
            ss[g][t] = g_srcn[j];
        }
    }
    __syncthreads();
    if (!ok) return;
    float4 acc = make_float4(0.f, 0.f, 0.f, 0.f);
#pragma unroll
    for (int k = 0; k < Kk; k++) {
        const float4* row = (const float4*)(Hin + (size_t)jj[g][k] * F);
        float4 v = row[t];
        float s = ss[g][k];
        acc.x = fmaf(v.x, s, acc.x);
        acc.y = fmaf(v.y, s, acc.y);
        acc.z = fmaf(v.z, s, acc.z);
        acc.w = fmaf(v.w, s, acc.w);
    }
    uint4 o;
    o.x = pack_split(acc.x * 0.25f);
    o.y = pack_split(acc.y * 0.25f);
    o.z = pack_split(acc.z * 0.25f);
    o.w = pack_split(acc.w * 0.25f);
    *(uint4*)(Sout + (size_t)node * F + t * 4) = o;
}

// ---------------- tensor-core GEMM -----------------
// smem row layout per k-step: [hi(16 bf16) | lo(16 bf16) | pad] = LDA2 halfwords
#define BM 128
#define BN 128
#define BK 16
#define LDA2 40

__global__ void __launch_bounds__(256, 2) mma_gemm_kernel(
    const uint32_t* __restrict__ A2, const uint32_t* __restrict__ B2,
    const float* __restrict__ bias, float* __restrict__ C,
    int M, int Kd, int Nc) {
    __shared__ __align__(16) uint16_t As[BM * LDA2];
    __shared__ __align__(16) uint16_t Bs[BN * LDA2];

    int t = threadIdx.x;
    int lane = t & 31;
    int wid = t >> 5;
    int m0 = blockIdx.y * BM;
    int n0 = blockIdx.x * BN;

    int wm = wid & 3;
    int wn = wid >> 2;
    int m_base = wm * 32;
    int n_base = wn * 64;

    uint32_t as_base = smem_u32(As);
    uint32_t bs_base = smem_u32(Bs);

    uint32_t aaddr[2], baddr[4];
#pragma unroll
    for (int f = 0; f < 2; f++) {
        int row = m_base + f * 16 + (lane & 7) + (lane & 8);
        int koff = (lane & 16) ? 16 : 0;
        aaddr[f] = as_base + row * (LDA2 * 2) + koff;
    }
#pragma unroll
    for (int p = 0; p < 4; p++) {
        int row = n_base + p * 16 + (lane & 7) + ((lane & 16) >> 1);
        int koff = (lane & 8) ? 16 : 0;
        baddr[p] = bs_base + row * (LDA2 * 2) + koff;
    }

    float acc[2][8][4];
#pragma unroll
    for (int f = 0; f < 2; f++)
#pragma unroll
        for (int nf = 0; nf < 8; nf++)
#pragma unroll
            for (int c = 0; c < 4; c++) acc[f][nf][c] = 0.0f;

    uint32_t* As32 = (uint32_t*)As;
    uint32_t* Bs32 = (uint32_t*)Bs;

    const int steps = Kd / BK;
    for (int s = 0; s < steps; s++) {
        int k0 = s * BK;
        // ---- fill A: [hi | lo] once ----
#pragma unroll
        for (int v = 0; v < 2; v++) {
            int vec = t + v * 256;
            int row = vec >> 2, q = vec & 3;
            int gm = m0 + row;
            uint4 d = make_uint4(0u, 0u, 0u, 0u);
            if (gm < M)
                d = *(const uint4*)(A2 + (size_t)gm * Kd + k0 + q * 4);
            uint32_t h0 = d.x & 0xffffu, l0 = d.x >> 16;
            uint32_t h1 = d.y & 0xffffu, l1 = d.y >> 16;
            uint32_t h2 = d.z & 0xffffu, l2 = d.z >> 16;
            uint32_t h3 = d.w & 0xffffu, l3 = d.w >> 16;
            int b32 = row * (LDA2 / 2) + 2 * q;
            As32[b32 + 0] = h0 | (h1 << 16);
            As32[b32 + 1] = h2 | (h3 << 16);
            As32[b32 + 8] = l0 | (l1 << 16);
            As32[b32 + 9] = l2 | (l3 << 16);
        }
        // ---- fill B: [hi | lo] once ----
#pragma unroll
        for (int v = 0; v < 2; v++) {
            int vec = t + v * 256;
            int row = vec >> 2, q = vec & 3;
            uint4 d = *(const uint4*)(B2 + (size_t)(n0 + row) * Kd + k0 + q * 4);
            uint32_t h0 = d.x & 0xffffu, l0 = d.x >> 16;
            uint32_t h1 = d.y & 0xffffu, l1 = d.y >> 16;
            uint32_t h2 = d.z & 0xffffu, l2 = d.z >> 16;
            uint32_t h3 = d.w & 0xffffu, l3 = d.w >> 16;
            int b32 = row * (LDA2 / 2) + 2 * q;
            Bs32[b32 + 0] = h0 | (h1 << 16);
            Bs32[b32 + 1] = h2 | (h3 << 16);
            Bs32[b32 + 8] = l0 | (l1 << 16);
            Bs32[b32 + 9] = l2 | (l3 << 16);
        }
        __syncthreads();

        // ---- compute: 3 products from register fragments ----
        {
            uint32_t a_h[2][4], a_l[2][4], b[4][4];
#pragma unroll
            for (int f = 0; f < 2; f++) ldsm4(a_h[f], aaddr[f]);
#pragma unroll
            for (int p = 0; p < 4; p++) ldsm4(b[p], baddr[p]);     // b_hi
#pragma unroll
            for (int f = 0; f < 2; f++)
#pragma unroll
                for (int p = 0; p < 4; p++) {
                    mma16816(acc[f][2 * p],     a_h[f], b[p][0], b[p][1]);
                    mma16816(acc[f][2 * p + 1], a_h[f], b[p][2], b[p][3]);
                }
#pragma unroll
            for (int f = 0; f < 2; f++) ldsm4(a_l[f], aaddr[f] + 32);
#pragma unroll
            for (int f = 0; f < 2; f++)
#pragma unroll
                for (int p = 0; p < 4; p++) {
                    mma16816(acc[f][2 * p],     a_l[f], b[p][0], b[p][1]);
                    mma16816(acc[f][2 * p + 1], a_l[f], b[p][2], b[p][3]);
                }
#pragma unroll
            for (int p = 0; p < 4; p++) ldsm4(b[p], baddr[p] + 32); // b_lo
#pragma unroll
            for (int f = 0; f < 2; f++)
#pragma unroll
                for (int p = 0; p < 4; p++) {
                    mma16816(acc[f][2 * p],     a_h[f], b[p][0], b[p][1]);
                    mma16816(acc[f][2 * p + 1], a_h[f], b[p][2], b[p][3]);
                }
        }
        __syncthreads();
    }

#pragma unroll
    for (int f = 0; f < 2; f++) {
#pragma unroll
        for (int nf = 0; nf < 8; nf++) {
            int col = n0 + n_base + nf * 8 + 2 * (lane & 3);
            float2 bv = *(const float2*)&bias[col];
            int row = m0 + m_base + f * 16 + (lane >> 2);
            if (row < M) {
                float2 o;
                o.x = fmaxf(acc[f][nf][0] + bv.x, 0.0f);
                o.y = fmaxf(acc[f][nf][1] + bv.y, 0.0f);
                *(float2*)(C + (size_t)row * Nc + col) = o;
            }
            int row2 = row + 8;
            if (row2 < M) {
                float2 o;
                o.x = fmaxf(acc[f][nf][2] + bv.x, 0.0f);
                o.y = fmaxf(acc[f][nf][3] + bv.y, 0.0f);
                *(float2*)(C + (size_t)row2 * Nc + col) = o;
            }
        }
    }
}

// out[i] = sigmoid(dot(h[i,:256], Wf) + bf) ; one warp per node
__global__ void final_kernel(const float* __restrict__ Hin,
                             const float* __restrict__ Wf,
                             const float* __restrict__ bf,
                             float* __restrict__ out) {
    int gwarp = (blockIdx.x * blockDim.x + threadIdx.x) >> 5;
    int lane = threadIdx.x & 31;
    if (gwarp >= Nn) return;
    float v = 0.0f;
#pragma unroll
    for (int tc = 0; tc < 8; tc++)
        v = fmaf(Hin[(size_t)gwarp * Hh + lane + tc * 32], Wf[lane + tc * 32], v);
#pragma unroll
    for (int off = 16; off > 0; off >>= 1)
        v += __shfl_xor_sync(FULLM, v, off);
    if (lane == 0) {
        float z = v + bf[0];
        out[gwarp] = 1.0f / (1.0f + expf(-z));
    }
}

// ---------------- host launcher --------------------
extern "C" void kernel_launch(void* const* d_in, const int* in_sizes, int n_in,
                              void* d_out, int out_size) {
    const float* x       = (const float*)d_in[0];
    const float* centers = (const float*)d_in[1];
    const float* W0      = (const float*)d_in[2];
    const float* b0      = (const float*)d_in[3];
    const float* W1      = (const float*)d_in[4];
    const float* b1      = (const float*)d_in[5];
    const float* W2      = (const float*)d_in[6];
    const float* b2      = (const float*)d_in[7];
    const float* Wf      = (const float*)d_in[8];
    const float* bf      = (const float*)d_in[9];
    float* out = (float*)d_out;
    (void)in_sizes; (void)n_in; (void)out_size;

    void *pH, *pS, *pW0, *pW1, *pW2, *pCnt, *pDeg;
    cudaGetSymbolAddress(&pH, g_bufH);
    cudaGetSymbolAddress(&pS, g_bufS);
    cudaGetSymbolAddress(&pW0, g_w0s);
    cudaGetSymbolAddress(&pW1, g_w1s);
    cudaGetSymbolAddress(&pW2, g_w2s);
    cudaGetSymbolAddress(&pCnt, g_cellCnt);
    cudaGetSymbolAddress(&pDeg, g_deg);
    float*    Hbuf = (float*)pH;
    uint32_t* Sbuf = (uint32_t*)pS;

    cudaMemsetAsync(pCnt, 0, NC * sizeof(int));
    cudaMemsetAsync(pDeg, 0, Nn * sizeof(int));
    convw_all_kernel<<<(Hh * Hh + 255) / 256, 256>>>(W0, W1, W2);
    assign_kernel<<<(Nn + 255) / 256, 256>>>(centers);
    scan_kernel<<<1, 1024>>>();
    scatter_kernel<<<(Nn + 255) / 256, 256>>>(centers);
    knn_kernel<<<(Nn * 32 + 255) / 256, 256>>>();
    deg_kernel<<<(Nn * Kk + 255) / 256, 256>>>();
    srcn_kernel<<<(Nn + 255) / 256, 256>>>();

    dim3 ggrid(Hh / BN, (Nn + BM - 1) / BM);

    // layer 0  (F=128: 8 nodes/block)
    aggregate_kernel<Dd><<<(Nn + 7) / 8, 256>>>(x, Sbuf);
    mma_gemm_kernel<<<ggrid, 256>>>(Sbuf, (uint32_t*)pW0, b0, Hbuf, Nn, Dd, Hh);

    // layer 1  (F=256: 4 nodes/block)
    aggregate_kernel<Hh><<<(Nn + 3) / 4, 256>>>(Hbuf, Sbuf);
    mma_gemm_kernel<<<ggrid, 256>>>(Sbuf, (uint32_t*)pW1, b1, Hbuf, Nn, Hh, Hh);

    // layer 2
    aggregate_kernel<Hh><<<(Nn + 3) / 4, 256>>>(Hbuf, Sbuf);
    mma_gemm_kernel<<<ggrid, 256>>>(Sbuf, (uint32_t*)pW2, b2, Hbuf, Nn, Hh, Hh);

    // final
    final_kernel<<<(Nn * 32 + 255) / 256, 256>>>(Hbuf, Wf, bf, out);
}

// round 9
// speedup vs baseline: 1.2025x; 1.0638x over previous
#include <cuda_runtime.h>
#include <cuda_bf16.h>
#include <math.h>
#include <stdint.h>

// ---------------- problem constants ----------------
#define Nn 20000
#define Dd 128
#define Hh 256
#define Kk 16

// ---------------- grid constants -------------------
#define GG 24
#define NC (GG * GG * GG)        // 13824
#define XMIN (-6.0f)
#define CELL (0.5f)
#define INV_CELL (2.0f)
#define FINF 3.4e38f
#define FULLM 0xffffffffu

// ---------------- scratch (static device) ----------
__device__ int   g_cellOf[Nn];
__device__ int   g_cellCnt[NC];
__device__ int   g_cellStart[NC + 1];
__device__ int   g_cellCur[NC];
__device__ float4 g_pts[Nn];      // (x, y, z, sq) sorted by cell
__device__ int   g_ptIdx[Nn];     // original index, sorted by cell
__device__ int   g_knn[Nn * Kk];
__device__ int   g_deg[Nn];
__device__ float g_srcn[Nn];
__device__ __align__(16) float    g_bufH[Nn * Hh];
__device__ __align__(16) uint32_t g_bufS[Nn * Hh];
__device__ __align__(16) uint32_t g_w0s[Dd * Hh];   // packed split W0^T [n][k]
__device__ __align__(16) uint32_t g_w1s[Hh * Hh];   // packed split W1^T
__device__ __align__(16) uint32_t g_w2s[Hh * Hh];   // packed split W2^T

// ---------------- small helpers --------------------
__device__ __forceinline__ int cellc(float v) {
    int c = (int)floorf((v - XMIN) * INV_CELL);
    return min(max(c, 0), GG - 1);
}

__device__ __forceinline__ uint32_t pack_split(float v) {
    __nv_bfloat16 h = __float2bfloat16(v);
    float hf = __bfloat162float(h);
    __nv_bfloat16 l = __float2bfloat16(v - hf);
    unsigned short hs = *reinterpret_cast<unsigned short*>(&h);
    unsigned short ls = *reinterpret_cast<unsigned short*>(&l);
    return (uint32_t)hs | ((uint32_t)ls << 16);
}

__device__ __forceinline__ uint32_t smem_u32(const void* p) {
    uint32_t a;
    asm("{ .reg .u64 t; cvta.to.shared.u64 t, %1; cvt.u32.u64 %0, t; }"
        : "=r"(a) : "l"(p));
    return a;
}

__device__ __forceinline__ void ldsm4(uint32_t* r, uint32_t addr) {
    asm volatile("ldmatrix.sync.aligned.m8n8.x4.shared.b16 {%0,%1,%2,%3}, [%4];"
                 : "=r"(r[0]), "=r"(r[1]), "=r"(r[2]), "=r"(r[3]) : "r"(addr));
}

__device__ __forceinline__ void mma16816(float* c, const uint32_t* a,
                                         const uint32_t b0, const uint32_t b1) {
    asm volatile(
        "mma.sync.aligned.m16n8k16.row.col.f32.bf16.bf16.f32 "
        "{%0,%1,%2,%3}, {%4,%5,%6,%7}, {%8,%9}, {%0,%1,%2,%3};"
        : "+f"(c[0]), "+f"(c[1]), "+f"(c[2]), "+f"(c[3])
        : "r"(a[0]), "r"(a[1]), "r"(a[2]), "r"(a[3]), "r"(b0), "r"(b1));
}

// ---------------- setup kernels --------------------

__global__ void assign_kernel(const float* __restrict__ centers) {
    int i = blockIdx.x * blockDim.x + threadIdx.x;
    if (i >= Nn) return;
    float x = centers[3 * i], y = centers[3 * i + 1], z = centers[3 * i + 2];
    int cid = (cellc(z) * GG + cellc(y)) * GG + cellc(x);
    g_cellOf[i] = cid;
    atomicAdd(&g_cellCnt[cid], 1);
}

__global__ void scan_kernel() {
    const int per = 14;   // 1024*14 = 14336 >= NC
    int t = threadIdx.x;
    int base = t * per;
    int s = 0;
    for (int i = 0; i < per; i++) {
        int idx = base + i;
        s += (idx < NC) ? g_cellCnt[idx] : 0;
    }

    int lane = t & 31, w = t >> 5;
    int v = s;
    for (int o = 1; o < 32; o <<= 1) {
        int n = __shfl_up_sync(FULLM, v, o);
        if (lane >= o) v += n;
    }
    __shared__ int ws[32];
    if (lane == 31) ws[w] = v;
    __syncthreads();
    if (w == 0) {
        int xv = ws[lane];
        for (int o = 1; o < 32; o <<= 1) {
            int n = __shfl_up_sync(FULLM, xv, o);
            if (lane >= o) xv += n;
        }
        ws[lane] = xv;
    }
    __syncthreads();
    int excl = v - s + (w ? ws[w - 1] : 0);
    int run = excl;
    for (int i = 0; i < per; i++) {
        int idx = base + i;
        if (idx < NC) {
            int c = g_cellCnt[idx];
            g_cellStart[idx] = run;
            g_cellCur[idx] = run;
            run += c;
        }
    }
    if (t == 1023) g_cellStart[NC] = Nn;
}

__global__ void scatter_kernel(const float* __restrict__ centers) {
    int i = blockIdx.x * blockDim.x + threadIdx.x;
    if (i >= Nn) return;
    int cid = g_cellOf[i];
    int pos = atomicAdd(&g_cellCur[cid], 1);
    float x = centers[3 * i], y = centers[3 * i + 1], z = centers[3 * i + 2];
    float sq = fmaf(z, z, fmaf(y, y, x * x));
    g_pts[pos] = make_float4(x, y, z, sq);
    g_ptIdx[pos] = i;
}

// ---------------- warp-per-query exact kNN ----------------
// Distributed sorted top-16 + row-level pruning with contiguous-run scans.
__global__ void __launch_bounds__(256) knn_kernel() {
    int gw = (blockIdx.x * blockDim.x + threadIdx.x) >> 5;
    int lane = threadIdx.x & 31;
    if (gw >= Nn) return;
    float4 q = g_pts[gw];
    int orig = g_ptIdx[gw];
    float qx = q.x, qy = q.y, qz = q.z, qsq = q.w;
    int cx = cellc(qx), cy = cellc(qy), cz = cellc(qz);

    float ld = FINF;   // distributed list: lane j = j-th smallest d2
    int   li = 0;
    float gth = FINF;  // current 16th-best (uniform)

    // contiguous-span scanner over cells [a, b] of one row
    auto scan_span = [&](int rowbase, int a, int b) {
        int p0 = g_cellStart[rowbase + a];
        int p1 = g_cellStart[rowbase + b + 1];
        for (int pb = p0; pb < p1; pb += 32) {
            int p = pb + lane;
            float d2 = FINF;
            int pid = 0;
            if (p < p1) {
                float4 c = g_pts[p];
                float t1 = fmaf(qx, c.x, fmaf(qy, c.y, qz * c.z));
                d2 = fmaf(-2.0f, t1, qsq + c.w);
                pid = g_ptIdx[p];
            }
            unsigned mask = __ballot_sync(FULLM, d2 < gth);
            while (mask) {
                int src = __ffs(mask) - 1;
                mask &= mask - 1;
                float nd = __shfl_sync(FULLM, d2, src);
                int   ni = __shfl_sync(FULLM, pid, src);
                if (nd >= gth) continue;           // uniform
                unsigned le = __ballot_sync(FULLM, ld <= nd);
                int pos = __popc(le);
                float pd = __shfl_up_sync(FULLM, ld, 1);
                int   pi = __shfl_up_sync(FULLM, li, 1);
                if (lane >= pos) { ld = pd; li = pi; }
                if (lane == pos) { ld = nd; li = ni; }
                gth = __shfl_sync(FULLM, ld, 15);
            }
        }
    };

    int Rcov = max(max(max(cx, GG - 1 - cx), max(cy, GG - 1 - cy)),
                   max(cz, GG - 1 - cz));

    for (int R = 0; R <= Rcov; R++) {
        int zlo = max(cz - R, 0), zhi = min(cz + R, GG - 1);
        int ylo = max(cy - R, 0), yhi = min(cy + R, GG - 1);
        int xlo = max(cx - R, 0), xhi = min(cx + R, GG - 1);
        for (int z = zlo; z <= zhi; z++) {
            int adz = abs(z - cz);
            float dz2 = 0.0f;
            bool pruning = (gth < FINF);
            if (pruning) {
                float zl = XMIN + (float)z * CELL;
                float dzd = fmaxf(fmaxf(zl - qz, qz - (zl + CELL)), 0.0f);
                dz2 = dzd * dzd;
                if (dz2 >= gth) continue;          // whole layer pruned
            }
            for (int y = ylo; y <= yhi; y++) {
                int dzy = max(adz, abs(y - cy));
                int rxlo = xlo, rxhi = xhi;        // allowed x-cell interval
                if (pruning) {
                    float yl = XMIN + (float)y * CELL;
                    float dyd = fmaxf(fmaxf(yl - qy, qy - (yl + CELL)), 0.0f);
                    float dzy2 = fmaf(dyd, dyd, dz2);
                    if (dzy2 >= gth) continue;     // row pruned
                    float rr = sqrtf(gth - dzy2);
                    rxlo = max(xlo, (int)floorf((qx - rr - XMIN) * INV_CELL) - 1);
                    rxhi = min(xhi, (int)floorf((qx + rr - XMIN) * INV_CELL) + 1);
                }
                int rowbase = (z * GG + y) * GG;
                if (dzy == R) {
                    if (rxlo <= rxhi) scan_span(rowbase, rxlo, rxhi);
                } else {
                    int xa = cx - R, xb = cx + R;
                    if (xa >= 0 && xa >= rxlo && xa <= rxhi)
                        scan_span(rowbase, xa, xa);
                    if (xb < GG && xb >= rxlo && xb <= rxhi)
                        scan_span(rowbase, xb, xb);
                }
            }
        }
        // stopping rule: gth is exact 16th best so far (uniform)
        if (gth < FINF) {
            float bx = fminf(qx - (XMIN + (float)(cx - R) * CELL),
                             (XMIN + (float)(cx + R + 1) * CELL) - qx);
            float by = fminf(qy - (XMIN + (float)(cy - R) * CELL),
                             (XMIN + (float)(cy + R + 1) * CELL) - qy);
            float bz = fminf(qz - (XMIN + (float)(cz - R) * CELL),
                             (XMIN + (float)(cz + R + 1) * CELL) - qz);
            float b = fmaxf(fminf(bx, fminf(by, bz)), 0.0f);
            if (gth <= b * b) break;
        }
    }

    if (lane < Kk) g_knn[orig * Kk + lane] = li;
}

__global__ void deg_kernel() {
    int e = blockIdx.x * blockDim.x + threadIdx.x;
    if (e < Nn * Kk) atomicAdd(&g_deg[g_knn[e]], 1);
}

__global__ void srcn_kernel() {
    int i = blockIdx.x * blockDim.x + threadIdx.x;
    if (i < Nn) g_srcn[i] = rsqrtf(fmaxf((float)g_deg[i], 1.0f));
}

// split-transpose of all three weight matrices in one launch
__global__ void convw_all_kernel(const float* __restrict__ W0,
                                 const float* __restrict__ W1,
                                 const float* __restrict__ W2) {
    int i = blockIdx.x * blockDim.x + threadIdx.x;
    if (i < Dd * Hh) {
        int k = i % Dd, n = i / Dd;
        g_w0s[(size_t)n * Dd + k] = pack_split(W0[(size_t)k * Hh + n]);
    }
    if (i < Hh * Hh) {
        int k = i % Hh, n = i / Hh;
        g_w1s[(size_t)n * Hh + k] = pack_split(W1[(size_t)k * Hh + n]);
        g_w2s[(size_t)n * Hh + k] = pack_split(W2[(size_t)k * Hh + n]);
    }
}

// agg[node, :] = 0.25 * sum_k h[knn[node,k], :] * srcn[knn[node,k]]  -> packed split
// Nodes processed in CELL-SORTED order (g_ptIdx) so co-scheduled nodes share
// neighbors and the gathers hit L1.
template <int F>
__global__ void __launch_bounds__(256) aggregate_kernel(
    const float* __restrict__ Hin, uint32_t* __restrict__ Sout) {
    const int TPN = F / 4;
    const int NPB = 256 / TPN;
    __shared__ int   jj[NPB][Kk];
    __shared__ float ss[NPB][Kk];
    int g = threadIdx.x / TPN;
    int t = threadIdx.x % TPN;
    int pos = blockIdx.x * NPB + g;
    bool ok = pos < Nn;
    int node = 0;
    if (ok) {
        node = g_ptIdx[pos];
        if (t < Kk) {
            int j = g_knn[node * Kk + t];
            jj[g][t] = j;
            ss[g][t] = g_srcn[j];
        }
    }
    __syncthreads();
    if (!ok) return;
    float4 acc = make_float4(0.f, 0.f, 0.f, 0.f);
#pragma unroll
    for (int k = 0; k < Kk; k++) {
        const float4* row = (const float4*)(Hin + (size_t)jj[g][k] * F);
        float4 v = row[t];
        float s = ss[g][k];
        acc.x = fmaf(v.x, s, acc.x);
        acc.y = fmaf(v.y, s, acc.y);
        acc.z = fmaf(v.z, s, acc.z);
        acc.w = fmaf(v.w, s, acc.w);
    }
    uint4 o;
    o.x = pack_split(acc.x * 0.25f);
    o.y = pack_split(acc.y * 0.25f);
    o.z = pack_split(acc.z * 0.25f);
    o.w = pack_split(acc.w * 0.25f);
    *(uint4*)(Sout + (size_t)node * F + t * 4) = o;
}

// ---------------- tensor-core GEMM -----------------
// smem row layout per k-step: [hi(16 bf16) | lo(16 bf16) | pad] = LDA2 halfwords
#define BM 128
#define BN 128
#define BK 16
#define LDA2 40

__global__ void __launch_bounds__(256, 2) mma_gemm_kernel(
    const uint32_t* __restrict__ A2, const uint32_t* __restrict__ B2,
    const float* __restrict__ bias, float* __restrict__ C,
    int M, int Kd, int Nc) {
    __shared__ __align__(16) uint16_t As[BM * LDA2];
    __shared__ __align__(16) uint16_t Bs[BN * LDA2];

    int t = threadIdx.x;
    int lane = t & 31;
    int wid = t >> 5;
    int m0 = blockIdx.y * BM;
    int n0 = blockIdx.x * BN;

    int wm = wid & 3;
    int wn = wid >> 2;
    int m_base = wm * 32;
    int n_base = wn * 64;

    uint32_t as_base = smem_u32(As);
    uint32_t bs_base = smem_u32(Bs);

    uint32_t aaddr[2], baddr[4];
#pragma unroll
    for (int f = 0; f < 2; f++) {
        int row = m_base + f * 16 + (lane & 7) + (lane & 8);
        int koff = (lane & 16) ? 16 : 0;
        aaddr[f] = as_base + row * (LDA2 * 2) + koff;
    }
#pragma unroll
    for (int p = 0; p < 4; p++) {
        int row = n_base + p * 16 + (lane & 7) + ((lane & 16) >> 1);
        int koff = (lane & 8) ? 16 : 0;
        baddr[p] = bs_base + row * (LDA2 * 2) + koff;
    }

    float acc[2][8][4];
#pragma unroll
    for (int f = 0; f < 2; f++)
#pragma unroll
        for (int nf = 0; nf < 8; nf++)
#pragma unroll
            for (int c = 0; c < 4; c++) acc[f][nf][c] = 0.0f;

    uint32_t* As32 = (uint32_t*)As;
    uint32_t* Bs32 = (uint32_t*)Bs;

    const int steps = Kd / BK;
    for (int s = 0; s < steps; s++) {
        int k0 = s * BK;
        // ---- fill A: [hi | lo] once ----
#pragma unroll
        for (int v = 0; v < 2; v++) {
            int vec = t + v * 256;
            int row = vec >> 2, q = vec & 3;
            int gm = m0 + row;
            uint4 d = make_uint4(0u, 0u, 0u, 0u);
            if (gm < M)
                d = *(const uint4*)(A2 + (size_t)gm * Kd + k0 + q * 4);
            uint32_t h0 = d.x & 0xffffu, l0 = d.x >> 16;
            uint32_t h1 = d.y & 0xffffu, l1 = d.y >> 16;
            uint32_t h2 = d.z & 0xffffu, l2 = d.z >> 16;
            uint32_t h3 = d.w & 0xffffu, l3 = d.w >> 16;
            int b32 = row * (LDA2 / 2) + 2 * q;
            As32[b32 + 0] = h0 | (h1 << 16);
            As32[b32 + 1] = h2 | (h3 << 16);
            As32[b32 + 8] = l0 | (l1 << 16);
            As32[b32 + 9] = l2 | (l3 << 16);
        }
        // ---- fill B: [hi | lo] once ----
#pragma unroll
        for (int v = 0; v < 2; v++) {
            int vec = t + v * 256;
            int row = vec >> 2, q = vec & 3;
            uint4 d = *(const uint4*)(B2 + (size_t)(n0 + row) * Kd + k0 + q * 4);
            uint32_t h0 = d.x & 0xffffu, l0 = d.x >> 16;
            uint32_t h1 = d.y & 0xffffu, l1 = d.y >> 16;
            uint32_t h2 = d.z & 0xffffu, l2 = d.z >> 16;
            uint32_t h3 = d.w & 0xffffu, l3 = d.w >> 16;
            int b32 = row * (LDA2 / 2) + 2 * q;
            Bs32[b32 + 0] = h0 | (h1 << 16);
            Bs32[b32 + 1] = h2 | (h3 << 16);
            Bs32[b32 + 8] = l0 | (l1 << 16);
            Bs32[b32 + 9] = l2 | (l3 << 16);
        }
        __syncthreads();

        // ---- compute: 3 products from register fragments ----
        {
            uint32_t a_h[2][4], a_l[2][4], b[4][4];
#pragma unroll
            for (int f = 0; f < 2; f++) ldsm4(a_h[f], aaddr[f]);
#pragma unroll
            for (int p = 0; p < 4; p++) ldsm4(b[p], baddr[p]);     // b_hi
#pragma unroll
            for (int f = 0; f < 2; f++)
#pragma unroll
                for (int p = 0; p < 4; p++) {
                    mma16816(acc[f][2 * p],     a_h[f], b[p][0], b[p][1]);
                    mma16816(acc[f][2 * p + 1], a_h[f], b[p][2], b[p][3]);
                }
#pragma unroll
            for (int f = 0; f < 2; f++) ldsm4(a_l[f], aaddr[f] + 32);
#pragma unroll
            for (int f = 0; f < 2; f++)
#pragma unroll
                for (int p = 0; p < 4; p++) {
                    mma16816(acc[f][2 * p],     a_l[f], b[p][0], b[p][1]);
                    mma16816(acc[f][2 * p + 1], a_l[f], b[p][2], b[p][3]);
                }
#pragma unroll
            for (int p = 0; p < 4; p++) ldsm4(b[p], baddr[p] + 32); // b_lo
#pragma unroll
            for (int f = 0; f < 2; f++)
#pragma unroll
                for (int p = 0; p < 4; p++) {
                    mma16816(acc[f][2 * p],     a_h[f], b[p][0], b[p][1]);
                    mma16816(acc[f][2 * p + 1], a_h[f], b[p][2], b[p][3]);
                }
        }
        __syncthreads();
    }

#pragma unroll
    for (int f = 0; f < 2; f++) {
#pragma unroll
        for (int nf = 0; nf < 8; nf++) {
            int col = n0 + n_base + nf * 8 + 2 * (lane & 3);
            float2 bv = *(const float2*)&bias[col];
            int row = m0 + m_base + f * 16 + (lane >> 2);
            if (row < M) {
                float2 o;
                o.x = fmaxf(acc[f][nf][0] + bv.x, 0.0f);
                o.y = fmaxf(acc[f][nf][1] + bv.y, 0.0f);
                *(float2*)(C + (size_t)row * Nc + col) = o;
            }
            int row2 = row + 8;
            if (row2 < M) {
                float2 o;
                o.x = fmaxf(acc[f][nf][2] + bv.x, 0.0f);
                o.y = fmaxf(acc[f][nf][3] + bv.y, 0.0f);
                *(float2*)(C + (size_t)row2 * Nc + col) = o;
            }
        }
    }
}

// out[i] = sigmoid(dot(h[i,:256], Wf) + bf) ; one warp per node
__global__ void final_kernel(const float* __restrict__ Hin,
                             const float* __restrict__ Wf,
                             const float* __restrict__ bf,
                             float* __restrict__ out) {
    int gwarp = (blockIdx.x * blockDim.x + threadIdx.x) >> 5;
    int lane = threadIdx.x & 31;
    if (gwarp >= Nn) return;
    float v = 0.0f;
#pragma unroll
    for (int tc = 0; tc < 8; tc++)
        v = fmaf(Hin[(size_t)gwarp * Hh + lane + tc * 32], Wf[lane + tc * 32], v);
#pragma unroll
    for (int off = 16; off > 0; off >>= 1)
        v += __shfl_xor_sync(FULLM, v, off);
    if (lane == 0) {
        float z = v + bf[0];
        out[gwarp] = 1.0f / (1.0f + expf(-z));
    }
}

// ---------------- host launcher --------------------
extern "C" void kernel_launch(void* const* d_in, const int* in_sizes, int n_in,
                              void* d_out, int out_size) {
    const float* x       = (const float*)d_in[0];
    const float* centers = (const float*)d_in[1];
    const float* W0      = (const float*)d_in[2];
    const float* b0      = (const float*)d_in[3];
    const float* W1      = (const float*)d_in[4];
    const float* b1      = (const float*)d_in[5];
    const float* W2      = (const float*)d_in[6];
    const float* b2      = (const float*)d_in[7];
    const float* Wf      = (const float*)d_in[8];
    const float* bf      = (const float*)d_in[9];
    float* out = (float*)d_out;
    (void)in_sizes; (void)n_in; (void)out_size;

    void *pH, *pS, *pW0, *pW1, *pW2, *pCnt, *pDeg;
    cudaGetSymbolAddress(&pH, g_bufH);
    cudaGetSymbolAddress(&pS, g_bufS);
    cudaGetSymbolAddress(&pW0, g_w0s);
    cudaGetSymbolAddress(&pW1, g_w1s);
    cudaGetSymbolAddress(&pW2, g_w2s);
    cudaGetSymbolAddress(&pCnt, g_cellCnt);
    cudaGetSymbolAddress(&pDeg, g_deg);
    float*    Hbuf = (float*)pH;
    uint32_t* Sbuf = (uint32_t*)pS;

    cudaMemsetAsync(pCnt, 0, NC * sizeof(int));
    cudaMemsetAsync(pDeg, 0, Nn * sizeof(int));
    convw_all_kernel<<<(Hh * Hh + 255) / 256, 256>>>(W0, W1, W2);
    assign_kernel<<<(Nn + 255) / 256, 256>>>(centers);
    scan_kernel<<<1, 1024>>>();
    scatter_kernel<<<(Nn + 255) / 256, 256>>>(centers);
    knn_kernel<<<(Nn * 32 + 255) / 256, 256>>>();
    deg_kernel<<<(Nn * Kk + 255) / 256, 256>>>();
    srcn_kernel<<<(Nn + 255) / 256, 256>>>();

    dim3 ggrid(Hh / BN, (Nn + BM - 1) / BM);

    // layer 0  (F=128: 8 nodes/block)
    aggregate_kernel<Dd><<<(Nn + 7) / 8, 256>>>(x, Sbuf);
    mma_gemm_kernel<<<ggrid, 256>>>(Sbuf, (uint32_t*)pW0, b0, Hbuf, Nn, Dd, Hh);

    // layer 1  (F=256: 4 nodes/block)
    aggregate_kernel<Hh><<<(Nn + 3) / 4, 256>>>(Hbuf, Sbuf);
    mma_gemm_kernel<<<ggrid, 256>>>(Sbuf, (uint32_t*)pW1, b1, Hbuf, Nn, Hh, Hh);

    // layer 2
    aggregate_kernel<Hh><<<(Nn + 3) / 4, 256>>>(Hbuf, Sbuf);
    mma_gemm_kernel<<<ggrid, 256>>>(Sbuf, (uint32_t*)pW2, b2, Hbuf, Nn, Hh, Hh);

    // final
    final_kernel<<<(Nn * 32 + 255) / 256, 256>>>(Hbuf, Wf, bf, out);
}

// round 10
// speedup vs baseline: 1.3067x; 1.0866x over previous
#include <cuda_runtime.h>
#include <cuda_bf16.h>
#include <math.h>
#include <stdint.h>

// ---------------- problem constants ----------------
#define Nn 20000
#define Dd 128
#define Hh 256
#define Kk 16

// ---------------- grid constants -------------------
#define GG 24
#define NC (GG * GG * GG)        // 13824
#define XMIN (-6.0f)
#define CELL (0.5f)
#define INV_CELL (2.0f)
#define FINF 3.4e38f
#define FULLM 0xffffffffu

// ---------------- scratch (static device) ----------
__device__ int   g_cellOf[Nn];
__device__ int   g_cellCnt[NC];
__device__ int   g_cellStart[NC + 1];
__device__ int   g_cellCur[NC];
__device__ float4 g_pts[Nn];      // (x, y, z, sq) sorted by cell
__device__ int   g_ptIdx[Nn];     // original index, sorted by cell
__device__ int   g_knn[Nn * Kk];
__device__ int   g_deg[Nn];
__device__ float g_srcn[Nn];
__device__ __align__(16) float    g_bufH[Nn * Hh];
__device__ __align__(16) uint32_t g_bufS[Nn * Hh];
__device__ __align__(16) uint32_t g_w0s[Dd * Hh];   // packed split W0^T [n][k]
__device__ __align__(16) uint32_t g_w1s[Hh * Hh];   // packed split W1^T
__device__ __align__(16) uint32_t g_w2s[Hh * Hh];   // packed split W2^T

// ---------------- small helpers --------------------
__device__ __forceinline__ int cellc(float v) {
    int c = (int)floorf((v - XMIN) * INV_CELL);
    return min(max(c, 0), GG - 1);
}

__device__ __forceinline__ uint32_t pack_split(float v) {
    __nv_bfloat16 h = __float2bfloat16(v);
    float hf = __bfloat162float(h);
    __nv_bfloat16 l = __float2bfloat16(v - hf);
    unsigned short hs = *reinterpret_cast<unsigned short*>(&h);
    unsigned short ls = *reinterpret_cast<unsigned short*>(&l);
    return (uint32_t)hs | ((uint32_t)ls << 16);
}

__device__ __forceinline__ uint32_t smem_u32(const void* p) {
    uint32_t a;
    asm("{ .reg .u64 t; cvta.to.shared.u64 t, %1; cvt.u32.u64 %0, t; }"
        : "=r"(a) : "l"(p));
    return a;
}

__device__ __forceinline__ void ldsm4(uint32_t* r, uint32_t addr) {
    asm volatile("ldmatrix.sync.aligned.m8n8.x4.shared.b16 {%0,%1,%2,%3}, [%4];"
                 : "=r"(r[0]), "=r"(r[1]), "=r"(r[2]), "=r"(r[3]) : "r"(addr));
}

__device__ __forceinline__ void mma16816(float* c, const uint32_t* a,
                                         const uint32_t b0, const uint32_t b1) {
    asm volatile(
        "mma.sync.aligned.m16n8k16.row.col.f32.bf16.bf16.f32 "
        "{%0,%1,%2,%3}, {%4,%5,%6,%7}, {%8,%9}, {%0,%1,%2,%3};"
        : "+f"(c[0]), "+f"(c[1]), "+f"(c[2]), "+f"(c[3])
        : "r"(a[0]), "r"(a[1]), "r"(a[2]), "r"(a[3]), "r"(b0), "r"(b1));
}

// ---------------- setup kernels --------------------

__global__ void assign_kernel(const float* __restrict__ centers) {
    int i = blockIdx.x * blockDim.x + threadIdx.x;
    if (i >= Nn) return;
    float x = centers[3 * i], y = centers[3 * i + 1], z = centers[3 * i + 2];
    int cid = (cellc(z) * GG + cellc(y)) * GG + cellc(x);
    g_cellOf[i] = cid;
    atomicAdd(&g_cellCnt[cid], 1);
}

__global__ void scan_kernel() {
    const int per = 14;   // 1024*14 = 14336 >= NC
    int t = threadIdx.x;
    int base = t * per;
    int s = 0;
    for (int i = 0; i < per; i++) {
        int idx = base + i;
        s += (idx < NC) ? g_cellCnt[idx] : 0;
    }

    int lane = t & 31, w = t >> 5;
    int v = s;
    for (int o = 1; o < 32; o <<= 1) {
        int n = __shfl_up_sync(FULLM, v, o);
        if (lane >= o) v += n;
    }
    __shared__ int ws[32];
    if (lane == 31) ws[w] = v;
    __syncthreads();
    if (w == 0) {
        int xv = ws[lane];
        for (int o = 1; o < 32; o <<= 1) {
            int n = __shfl_up_sync(FULLM, xv, o);
            if (lane >= o) xv += n;
        }
        ws[lane] = xv;
    }
    __syncthreads();
    int excl = v - s + (w ? ws[w - 1] : 0);
    int run = excl;
    for (int i = 0; i < per; i++) {
        int idx = base + i;
        if (idx < NC) {
            int c = g_cellCnt[idx];
            g_cellStart[idx] = run;
            g_cellCur[idx] = run;
            run += c;
        }
    }
    if (t == 1023) g_cellStart[NC] = Nn;
}

__global__ void scatter_kernel(const float* __restrict__ centers) {
    int i = blockIdx.x * blockDim.x + threadIdx.x;
    if (i >= Nn) return;
    int cid = g_cellOf[i];
    int pos = atomicAdd(&g_cellCur[cid], 1);
    float x = centers[3 * i], y = centers[3 * i + 1], z = centers[3 * i + 2];
    float sq = fmaf(z, z, fmaf(y, y, x * x));
    g_pts[pos] = make_float4(x, y, z, sq);
    g_ptIdx[pos] = i;
}

// ---------------- warp-per-query exact kNN ----------------
// Distributed sorted top-16 + row-level pruning with contiguous-run scans.
// Out-degree atomics fused into the tail.
__global__ void __launch_bounds__(256) knn_kernel() {
    int gw = (blockIdx.x * blockDim.x + threadIdx.x) >> 5;
    int lane = threadIdx.x & 31;
    if (gw >= Nn) return;
    float4 q = g_pts[gw];
    int orig = g_ptIdx[gw];
    float qx = q.x, qy = q.y, qz = q.z, qsq = q.w;
    int cx = cellc(qx), cy = cellc(qy), cz = cellc(qz);

    float ld = FINF;   // distributed list: lane j = j-th smallest d2
    int   li = 0;
    float gth = FINF;  // current 16th-best (uniform)

    auto scan_span = [&](int rowbase, int a, int b) {
        int p0 = g_cellStart[rowbase + a];
        int p1 = g_cellStart[rowbase + b + 1];
        for (int pb = p0; pb < p1; pb += 32) {
            int p = pb + lane;
            float d2 = FINF;
            int pid = 0;
            if (p < p1) {
                float4 c = g_pts[p];
                float t1 = fmaf(qx, c.x, fmaf(qy, c.y, qz * c.z));
                d2 = fmaf(-2.0f, t1, qsq + c.w);
                pid = g_ptIdx[p];
            }
            unsigned mask = __ballot_sync(FULLM, d2 < gth);
            while (mask) {
                int src = __ffs(mask) - 1;
                mask &= mask - 1;
                float nd = __shfl_sync(FULLM, d2, src);
                int   ni = __shfl_sync(FULLM, pid, src);
                if (nd >= gth) continue;           // uniform
                unsigned le = __ballot_sync(FULLM, ld <= nd);
                int pos = __popc(le);
                float pd = __shfl_up_sync(FULLM, ld, 1);
                int   pi = __shfl_up_sync(FULLM, li, 1);
                if (lane >= pos) { ld = pd; li = pi; }
                if (lane == pos) { ld = nd; li = ni; }
                gth = __shfl_sync(FULLM, ld, 15);
            }
        }
    };

    int Rcov = max(max(max(cx, GG - 1 - cx), max(cy, GG - 1 - cy)),
                   max(cz, GG - 1 - cz));

    for (int R = 0; R <= Rcov; R++) {
        int zlo = max(cz - R, 0), zhi = min(cz + R, GG - 1);
        int ylo = max(cy - R, 0), yhi = min(cy + R, GG - 1);
        int xlo = max(cx - R, 0), xhi = min(cx + R, GG - 1);
        for (int z = zlo; z <= zhi; z++) {
            int adz = abs(z - cz);
            float dz2 = 0.0f;
            bool pruning = (gth < FINF);
            if (pruning) {
                float zl = XMIN + (float)z * CELL;
                float dzd = fmaxf(fmaxf(zl - qz, qz - (zl + CELL)), 0.0f);
                dz2 = dzd * dzd;
                if (dz2 >= gth) continue;          // whole layer pruned
            }
            for (int y = ylo; y <= yhi; y++) {
                int dzy = max(adz, abs(y - cy));
                int rxlo = xlo, rxhi = xhi;
                if (pruning) {
                    float yl = XMIN + (float)y * CELL;
                    float dyd = fmaxf(fmaxf(yl - qy, qy - (yl + CELL)), 0.0f);
                    float dzy2 = fmaf(dyd, dyd, dz2);
                    if (dzy2 >= gth) continue;     // row pruned
                    float rr = sqrtf(gth - dzy2);
                    rxlo = max(xlo, (int)floorf((qx - rr - XMIN) * INV_CELL) - 1);
                    rxhi = min(xhi, (int)floorf((qx + rr - XMIN) * INV_CELL) + 1);
                }
                int rowbase = (z * GG + y) * GG;
                if (dzy == R) {
                    if (rxlo <= rxhi) scan_span(rowbase, rxlo, rxhi);
                } else {
                    int xa = cx - R, xb = cx + R;
                    if (xa >= 0 && xa >= rxlo && xa <= rxhi)
                        scan_span(rowbase, xa, xa);
                    if (xb < GG && xb >= rxlo && xb <= rxhi)
                        scan_span(rowbase, xb, xb);
                }
            }
        }
        if (gth < FINF) {
            float bx = fminf(qx - (XMIN + (float)(cx - R) * CELL),
                             (XMIN + (float)(cx + R + 1) * CELL) - qx);
            float by = fminf(qy - (XMIN + (float)(cy - R) * CELL),
                             (XMIN + (float)(cy + R + 1) * CELL) - qy);
            float bz = fminf(qz - (XMIN + (float)(cz - R) * CELL),
                             (XMIN + (float)(cz + R + 1) * CELL) - qz);
            float b = fmaxf(fminf(bx, fminf(by, bz)), 0.0f);
            if (gth <= b * b) break;
        }
    }

    if (lane < Kk) {
        g_knn[orig * Kk + lane] = li;
        atomicAdd(&g_deg[li], 1);       // fused out-degree
    }
}

__global__ void srcn_kernel() {
    int i = blockIdx.x * blockDim.x + threadIdx.x;
    if (i < Nn) g_srcn[i] = rsqrtf(fmaxf((float)g_deg[i], 1.0f));
}

// split-transpose of all three weight matrices in one launch
__global__ void convw_all_kernel(const float* __restrict__ W0,
                                 const float* __restrict__ W1,
                                 const float* __restrict__ W2) {
    int i = blockIdx.x * blockDim.x + threadIdx.x;
    if (i < Dd * Hh) {
        int k = i % Dd, n = i / Dd;
        g_w0s[(size_t)n * Dd + k] = pack_split(W0[(size_t)k * Hh + n]);
    }
    if (i < Hh * Hh) {
        int k = i % Hh, n = i / Hh;
        g_w1s[(size_t)n * Hh + k] = pack_split(W1[(size_t)k * Hh + n]);
        g_w2s[(size_t)n * Hh + k] = pack_split(W2[(size_t)k * Hh + n]);
    }
}

// agg in cell-sorted order; float4 vectorized
template <int F>
__global__ void __launch_bounds__(256) aggregate_kernel(
    const float* __restrict__ Hin, uint32_t* __restrict__ Sout) {
    const int TPN = F / 4;
    const int NPB = 256 / TPN;
    __shared__ int   jj[NPB][Kk];
    __shared__ float ss[NPB][Kk];
    int g = threadIdx.x / TPN;
    int t = threadIdx.x % TPN;
    int pos = blockIdx.x * NPB + g;
    bool ok = pos < Nn;
    int node = 0;
    if (ok) {
        node = g_ptIdx[pos];
        if (t < Kk) {
            int j = g_knn[node * Kk + t];
            jj[g][t] = j;
            ss[g][t] = g_srcn[j];
        }
    }
    __syncthreads();
    if (!ok) return;
    float4 acc = make_float4(0.f, 0.f, 0.f, 0.f);
#pragma unroll
    for (int k = 0; k < Kk; k++) {
        const float4* row = (const float4*)(Hin + (size_t)jj[g][k] * F);
        float4 v = row[t];
        float s = ss[g][k];
        acc.x = fmaf(v.x, s, acc.x);
        acc.y = fmaf(v.y, s, acc.y);
        acc.z = fmaf(v.z, s, acc.z);
        acc.w = fmaf(v.w, s, acc.w);
    }
    uint4 o;
    o.x = pack_split(acc.x * 0.25f);
    o.y = pack_split(acc.y * 0.25f);
    o.z = pack_split(acc.z * 0.25f);
    o.w = pack_split(acc.w * 0.25f);
    *(uint4*)(Sout + (size_t)node * F + t * 4) = o;
}

// ---------------- tensor-core GEMM (double-buffered) -----------------
#define BM 128
#define BN 128
#define BK 16
#define LDA2 40

__global__ void __launch_bounds__(256, 2) mma_gemm_kernel(
    const uint32_t* __restrict__ A2, const uint32_t* __restrict__ B2,
    const float* __restrict__ bias, float* __restrict__ C,
    int M, int Kd, int Nc) {
    __shared__ __align__(16) uint16_t As[2][BM * LDA2];
    __shared__ __align__(16) uint16_t Bs[2][BN * LDA2];

    int t = threadIdx.x;
    int lane = t & 31;
    int wid = t >> 5;
    int m0 = blockIdx.y * BM;
    int n0 = blockIdx.x * BN;

    int wm = wid & 3;
    int wn = wid >> 2;
    int m_base = wm * 32;
    int n_base = wn * 64;

    uint32_t as_base = smem_u32(As);
    uint32_t bs_base = smem_u32(Bs);
    const uint32_t aBufStride = BM * LDA2 * 2;   // bytes
    const uint32_t bBufStride = BN * LDA2 * 2;

    uint32_t aaddr[2], baddr[4];
#pragma unroll
    for (int f = 0; f < 2; f++) {
        int row = m_base + f * 16 + (lane & 7) + (lane & 8);
        int koff = (lane & 16) ? 16 : 0;
        aaddr[f] = as_base + row * (LDA2 * 2) + koff;
    }
#pragma unroll
    for (int p = 0; p < 4; p++) {
        int row = n_base + p * 16 + (lane & 7) + ((lane & 16) >> 1);
        int koff = (lane & 8) ? 16 : 0;
        baddr[p] = bs_base + row * (LDA2 * 2) + koff;
    }

    // per-thread fill coordinates
    int fr0 = t >> 2, fq0 = t & 3;            // vec = t
    int fr1 = (t + 256) >> 2, fq1 = (t + 256) & 3;

    float acc[2][8][4];
#pragma unroll
    for (int f = 0; f < 2; f++)
#pragma unroll
        for (int nf = 0; nf < 8; nf++)
#pragma unroll
            for (int c = 0; c < 4; c++) acc[f][nf][c] = 0.0f;

    uint32_t* As32 = (uint32_t*)As;
    uint32_t* Bs32 = (uint32_t*)Bs;
    const int aBuf32 = BM * LDA2 / 2;          // uint32 per A buffer
    const int bBuf32 = BN * LDA2 / 2;

    auto fetch = [&](int s, uint4* ra, uint4* rb) {
        int k0 = s * BK;
        int gm0 = m0 + fr0;
        ra[0] = (gm0 < M) ? *(const uint4*)(A2 + (size_t)gm0 * Kd + k0 + fq0 * 4)
                          : make_uint4(0u, 0u, 0u, 0u);
        int gm1 = m0 + fr1;
        ra[1] = (gm1 < M) ? *(const uint4*)(A2 + (size_t)gm1 * Kd + k0 + fq1 * 4)
                          : make_uint4(0u, 0u, 0u, 0u);
        rb[0] = *(const uint4*)(B2 + (size_t)(n0 + fr0) * Kd + k0 + fq0 * 4);
        rb[1] = *(const uint4*)(B2 + (size_t)(n0 + fr1) * Kd + k0 + fq1 * 4);
    };
    auto unp_store = [&](uint32_t* dst, int b32, uint4 d) {
        uint32_t h0 = d.x & 0xffffu, l0 = d.x >> 16;
        uint32_t h1 = d.y & 0xffffu, l1 = d.y >> 16;
        uint32_t h2 = d.z & 0xffffu, l2 = d.z >> 16;
        uint32_t h3 = d.w & 0xffffu, l3 = d.w >> 16;
        dst[b32 + 0] = h0 | (h1 << 16);
        dst[b32 + 1] = h2 | (h3 << 16);
        dst[b32 + 8] = l0 | (l1 << 16);
        dst[b32 + 9] = l2 | (l3 << 16);
    };
    auto store_buf = [&](int buf, uint4* ra, uint4* rb) {
        unp_store(As32 + buf * aBuf32, fr0 * (LDA2 / 2) + 2 * fq0, ra[0]);
        unp_store(As32 + buf * aBuf32, fr1 * (LDA2 / 2) + 2 * fq1, ra[1]);
        unp_store(Bs32 + buf * bBuf32, fr0 * (LDA2 / 2) + 2 * fq0, rb[0]);
        unp_store(Bs32 + buf * bBuf32, fr1 * (LDA2 / 2) + 2 * fq1, rb[1]);
    };
    auto compute = [&](int buf) {
        uint32_t aoff = buf * aBufStride;
        uint32_t boff = buf * bBufStride;
        uint32_t a_h[2][4], a_l[2][4], b[4][4];
#pragma unroll
        for (int f = 0; f < 2; f++) ldsm4(a_h[f], aaddr[f] + aoff);
#pragma unroll
        for (int p = 0; p < 4; p++) ldsm4(b[p], baddr[p] + boff);   // b_hi
#pragma unroll
        for (int f = 0; f < 2; f++)
#pragma unroll
            for (int p = 0; p < 4; p++) {
                mma16816(acc[f][2 * p],     a_h[f], b[p][0], b[p][1]);
                mma16816(acc[f][2 * p + 1], a_h[f], b[p][2], b[p][3]);
            }
#pragma unroll
        for (int f = 0; f < 2; f++) ldsm4(a_l[f], aaddr[f] + aoff + 32);
#pragma unroll
        for (int f = 0; f < 2; f++)
#pragma unroll
            for (int p = 0; p < 4; p++) {
                mma16816(acc[f][2 * p],     a_l[f], b[p][0], b[p][1]);
                mma16816(acc[f][2 * p + 1], a_l[f], b[p][2], b[p][3]);
            }
#pragma unroll
        for (int p = 0; p < 4; p++) ldsm4(b[p], baddr[p] + boff + 32); // b_lo
#pragma unroll
        for (int f = 0; f < 2; f++)
#pragma unroll
            for (int p = 0; p < 4; p++) {
                mma16816(acc[f][2 * p],     a_h[f], b[p][0], b[p][1]);
                mma16816(acc[f][2 * p + 1], a_h[f], b[p][2], b[p][3]);
            }
    };

    const int steps = Kd / BK;
    uint4 ra[2], rb[2];
    fetch(0, ra, rb);
    store_buf(0, ra, rb);
    __syncthreads();
    for (int s = 0; s < steps; s++) {
        bool more = (s + 1 < steps);
        if (more) fetch(s + 1, ra, rb);
        compute(s & 1);
        if (more) {
            store_buf((s + 1) & 1, ra, rb);
            __syncthreads();
        }
    }

#pragma unroll
    for (int f = 0; f < 2; f++) {
#pragma unroll
        for (int nf = 0; nf < 8; nf++) {
            int col = n0 + n_base + nf * 8 + 2 * (lane & 3);
            float2 bv = *(const float2*)&bias[col];
            int row = m0 + m_base + f * 16 + (lane >> 2);
            if (row < M) {
                float2 o;
                o.x = fmaxf(acc[f][nf][0] + bv.x, 0.0f);
                o.y = fmaxf(acc[f][nf][1] + bv.y, 0.0f);
                *(float2*)(C + (size_t)row * Nc + col) = o;
            }
            int row2 = row + 8;
            if (row2 < M) {
                float2 o;
                o.x = fmaxf(acc[f][nf][2] + bv.x, 0.0f);
                o.y = fmaxf(acc[f][nf][3] + bv.y, 0.0f);
                *(float2*)(C + (size_t)row2 * Nc + col) = o;
            }
        }
    }
}

// out[i] = sigmoid(dot(h[i,:256], Wf) + bf) ; one warp per node, float4 loads
__global__ void final_kernel(const float* __restrict__ Hin,
                             const float* __restrict__ Wf,
                             const float* __restrict__ bf,
                             float* __restrict__ out) {
    int gwarp = (blockIdx.x * blockDim.x + threadIdx.x) >> 5;
    int lane = threadIdx.x & 31;
    if (gwarp >= Nn) return;
    const float4* hrow = (const float4*)(Hin + (size_t)gwarp * Hh);
    const float4* wrow = (const float4*)Wf;
    float v = 0.0f;
#pragma unroll
    for (int c = 0; c < 2; c++) {
        float4 h4 = hrow[lane + c * 32];
        float4 w4 = wrow[lane + c * 32];
        v = fmaf(h4.x, w4.x, v);
        v = fmaf(h4.y, w4.y, v);
        v = fmaf(h4.z, w4.z, v);
        v = fmaf(h4.w, w4.w, v);
    }
#pragma unroll
    for (int off = 16; off > 0; off >>= 1)
        v += __shfl_xor_sync(FULLM, v, off);
    if (lane == 0) {
        float z = v + bf[0];
        out[gwarp] = 1.0f / (1.0f + expf(-z));
    }
}

// ---------------- host launcher --------------------
extern "C" void kernel_launch(void* const* d_in, const int* in_sizes, int n_in,
                              void* d_out, int out_size) {
    const float* x       = (const float*)d_in[0];
    const float* centers = (const float*)d_in[1];
    const float* W0      = (const float*)d_in[2];
    const float* b0      = (const float*)d_in[3];
    const float* W1      = (const float*)d_in[4];
    const float* b1      = (const float*)d_in[5];
    const float* W2      = (const float*)d_in[6];
    const float* b2      = (const float*)d_in[7];
    const float* Wf      = (const float*)d_in[8];
    const float* bf      = (const float*)d_in[9];
    float* out = (float*)d_out;
    (void)in_sizes; (void)n_in; (void)out_size;

    void *pH, *pS, *pW0, *pW1, *pW2, *pCnt, *pDeg;
    cudaGetSymbolAddress(&pH, g_bufH);
    cudaGetSymbolAddress(&pS, g_bufS);
    cudaGetSymbolAddress(&pW0, g_w0s);
    cudaGetSymbolAddress(&pW1, g_w1s);
    cudaGetSymbolAddress(&pW2, g_w2s);
    cudaGetSymbolAddress(&pCnt, g_cellCnt);
    cudaGetSymbolAddress(&pDeg, g_deg);
    float*    Hbuf = (float*)pH;
    uint32_t* Sbuf = (uint32_t*)pS;

    cudaMemsetAsync(pCnt, 0, NC * sizeof(int));
    cudaMemsetAsync(pDeg, 0, Nn * sizeof(int));
    convw_all_kernel<<<(Hh * Hh + 255) / 256, 256>>>(W0, W1, W2);
    assign_kernel<<<(Nn + 255) / 256, 256>>>(centers);
    scan_kernel<<<1, 1024>>>();
    scatter_kernel<<<(Nn + 255) / 256, 256>>>(centers);
    knn_kernel<<<(Nn * 32 + 255) / 256, 256>>>();
    srcn_kernel<<<(Nn + 255) / 256, 256>>>();

    dim3 ggrid(Hh / BN, (Nn + BM - 1) / BM);

    // layer 0  (F=128: 8 nodes/block)
    aggregate_kernel<Dd><<<(Nn + 7) / 8, 256>>>(x, Sbuf);
    mma_gemm_kernel<<<ggrid, 256>>>(Sbuf, (uint32_t*)pW0, b0, Hbuf, Nn, Dd, Hh);

    // layer 1  (F=256: 4 nodes/block)
    aggregate_kernel<Hh><<<(Nn + 3) / 4, 256>>>(Hbuf, Sbuf);
    mma_gemm_kernel<<<ggrid, 256>>>(Sbuf, (uint32_t*)pW1, b1, Hbuf, Nn, Hh, Hh);

    // layer 2
    aggregate_kernel<Hh><<<(Nn + 3) / 4, 256>>>(Hbuf, Sbuf);
    mma_gemm_kernel<<<ggrid, 256>>>(Sbuf, (uint32_t*)pW2, b2, Hbuf, Nn, Hh, Hh);

    // final
    final_kernel<<<(Nn * 32 + 255) / 256, 256>>>(Hbuf, Wf, bf, out);
}

// round 11
// speedup vs baseline: 1.3295x; 1.0175x over previous
#include <cuda_runtime.h>
#include <cuda_bf16.h>
#include <math.h>
#include <stdint.h>

// ---------------- problem constants ----------------
#define Nn 20000
#define Dd 128
#define Hh 256
#define Kk 16

// ---------------- grid constants -------------------
#define GG 24
#define NC (GG * GG * GG)        // 13824
#define XMIN (-6.0f)
#define CELL (0.5f)
#define INV_CELL (2.0f)
#define FINF 3.4e38f
#define FULLM 0xffffffffu

// ---------------- scratch (static device) ----------
__device__ int   g_cellOf[Nn];
__device__ int   g_cellCnt[NC];
__device__ int   g_cellStart[NC + 1];
__device__ int   g_cellCur[NC];
__device__ float4 g_pts[Nn];      // (x, y, z, sq) sorted by cell
__device__ int   g_ptIdx[Nn];     // original index, sorted by cell
__device__ int   g_knn[Nn * Kk];
__device__ int   g_deg[Nn];
__device__ __align__(16) float    g_bufH[Nn * Hh];   // hidden acts; head reused for partials
__device__ __align__(16) uint32_t g_bufS[Nn * Hh];
__device__ __align__(16) uint32_t g_w0s[Dd * Hh];   // packed split W0^T [n][k]
__device__ __align__(16) uint32_t g_w1s[Hh * Hh];   // packed split W1^T
__device__ __align__(16) uint32_t g_w2s[Hh * Hh];   // packed split W2^T
__device__ __align__(16) float    g_part[2 * Nn];    // fused-final partials

// ---------------- small helpers --------------------
__device__ __forceinline__ int cellc(float v) {
    int c = (int)floorf((v - XMIN) * INV_CELL);
    return min(max(c, 0), GG - 1);
}

__device__ __forceinline__ uint32_t pack_split(float v) {
    __nv_bfloat16 h = __float2bfloat16(v);
    float hf = __bfloat162float(h);
    __nv_bfloat16 l = __float2bfloat16(v - hf);
    unsigned short hs = *reinterpret_cast<unsigned short*>(&h);
    unsigned short ls = *reinterpret_cast<unsigned short*>(&l);
    return (uint32_t)hs | ((uint32_t)ls << 16);
}

__device__ __forceinline__ uint32_t smem_u32(const void* p) {
    uint32_t a;
    asm("{ .reg .u64 t; cvta.to.shared.u64 t, %1; cvt.u32.u64 %0, t; }"
        : "=r"(a) : "l"(p));
    return a;
}

__device__ __forceinline__ void ldsm4(uint32_t* r, uint32_t addr) {
    asm volatile("ldmatrix.sync.aligned.m8n8.x4.shared.b16 {%0,%1,%2,%3}, [%4];"
                 : "=r"(r[0]), "=r"(r[1]), "=r"(r[2]), "=r"(r[3]) : "r"(addr));
}

__device__ __forceinline__ void mma16816(float* c, const uint32_t* a,
                                         const uint32_t b0, const uint32_t b1) {
    asm volatile(
        "mma.sync.aligned.m16n8k16.row.col.f32.bf16.bf16.f32 "
        "{%0,%1,%2,%3}, {%4,%5,%6,%7}, {%8,%9}, {%0,%1,%2,%3};"
        : "+f"(c[0]), "+f"(c[1]), "+f"(c[2]), "+f"(c[3])
        : "r"(a[0]), "r"(a[1]), "r"(a[2]), "r"(a[3]), "r"(b0), "r"(b1));
}

// ---------------- setup kernels --------------------

__global__ void assign_kernel(const float* __restrict__ centers) {
    int i = blockIdx.x * blockDim.x + threadIdx.x;
    if (i >= Nn) return;
    float x = centers[3 * i], y = centers[3 * i + 1], z = centers[3 * i + 2];
    int cid = (cellc(z) * GG + cellc(y)) * GG + cellc(x);
    g_cellOf[i] = cid;
    atomicAdd(&g_cellCnt[cid], 1);
}

__global__ void scan_kernel() {
    const int per = 14;   // 1024*14 = 14336 >= NC
    int t = threadIdx.x;
    int base = t * per;
    int s = 0;
    for (int i = 0; i < per; i++) {
        int idx = base + i;
        s += (idx < NC) ? g_cellCnt[idx] : 0;
    }

    int lane = t & 31, w = t >> 5;
    int v = s;
    for (int o = 1; o < 32; o <<= 1) {
        int n = __shfl_up_sync(FULLM, v, o);
        if (lane >= o) v += n;
    }
    __shared__ int ws[32];
    if (lane == 31) ws[w] = v;
    __syncthreads();
    if (w == 0) {
        int xv = ws[lane];
        for (int o = 1; o < 32; o <<= 1) {
            int n = __shfl_up_sync(FULLM, xv, o);
            if (lane >= o) xv += n;
        }
        ws[lane] = xv;
    }
    __syncthreads();
    int excl = v - s + (w ? ws[w - 1] : 0);
    int run = excl;
    for (int i = 0; i < per; i++) {
        int idx = base + i;
        if (idx < NC) {
            int c = g_cellCnt[idx];
            g_cellStart[idx] = run;
            g_cellCur[idx] = run;
            run += c;
        }
    }
    if (t == 1023) g_cellStart[NC] = Nn;
}

__global__ void scatter_kernel(const float* __restrict__ centers) {
    int i = blockIdx.x * blockDim.x + threadIdx.x;
    if (i >= Nn) return;
    int cid = g_cellOf[i];
    int pos = atomicAdd(&g_cellCur[cid], 1);
    float x = centers[3 * i], y = centers[3 * i + 1], z = centers[3 * i + 2];
    float sq = fmaf(z, z, fmaf(y, y, x * x));
    g_pts[pos] = make_float4(x, y, z, sq);
    g_ptIdx[pos] = i;
}

// ---------------- warp-per-query exact kNN ----------------
__global__ void __launch_bounds__(256) knn_kernel() {
    int gw = (blockIdx.x * blockDim.x + threadIdx.x) >> 5;
    int lane = threadIdx.x & 31;
    if (gw >= Nn) return;
    float4 q = g_pts[gw];
    int orig = g_ptIdx[gw];
    float qx = q.x, qy = q.y, qz = q.z, qsq = q.w;
    int cx = cellc(qx), cy = cellc(qy), cz = cellc(qz);

    float ld = FINF;
    int   li = 0;
    float gth = FINF;

    auto scan_span = [&](int rowbase, int a, int b) {
        int p0 = g_cellStart[rowbase + a];
        int p1 = g_cellStart[rowbase + b + 1];
        for (int pb = p0; pb < p1; pb += 32) {
            int p = pb + lane;
            float d2 = FINF;
            int pid = 0;
            if (p < p1) {
                float4 c = g_pts[p];
                float t1 = fmaf(qx, c.x, fmaf(qy, c.y, qz * c.z));
                d2 = fmaf(-2.0f, t1, qsq + c.w);
                pid = g_ptIdx[p];
            }
            unsigned mask = __ballot_sync(FULLM, d2 < gth);
            while (mask) {
                int src = __ffs(mask) - 1;
                mask &= mask - 1;
                float nd = __shfl_sync(FULLM, d2, src);
                int   ni = __shfl_sync(FULLM, pid, src);
                if (nd >= gth) continue;
                unsigned le = __ballot_sync(FULLM, ld <= nd);
                int pos = __popc(le);
                float pd = __shfl_up_sync(FULLM, ld, 1);
                int   pi = __shfl_up_sync(FULLM, li, 1);
                if (lane >= pos) { ld = pd; li = pi; }
                if (lane == pos) { ld = nd; li = ni; }
                gth = __shfl_sync(FULLM, ld, 15);
            }
        }
    };

    int Rcov = max(max(max(cx, GG - 1 - cx), max(cy, GG - 1 - cy)),
                   max(cz, GG - 1 - cz));

    for (int R = 0; R <= Rcov; R++) {
        int zlo = max(cz - R, 0), zhi = min(cz + R, GG - 1);
        int ylo = max(cy - R, 0), yhi = min(cy + R, GG - 1);
        int xlo = max(cx - R, 0), xhi = min(cx + R, GG - 1);
        for (int z = zlo; z <= zhi; z++) {
            int adz = abs(z - cz);
            float dz2 = 0.0f;
            bool pruning = (gth < FINF);
            if (pruning) {
                float zl = XMIN + (float)z * CELL;
                float dzd = fmaxf(fmaxf(zl - qz, qz - (zl + CELL)), 0.0f);
                dz2 = dzd * dzd;
                if (dz2 >= gth) continue;
            }
            for (int y = ylo; y <= yhi; y++) {
                int dzy = max(adz, abs(y - cy));
                int rxlo = xlo, rxhi = xhi;
                if (pruning) {
                    float yl = XMIN + (float)y * CELL;
                    float dyd = fmaxf(fmaxf(yl - qy, qy - (yl + CELL)), 0.0f);
                    float dzy2 = fmaf(dyd, dyd, dz2);
                    if (dzy2 >= gth) continue;
                    float rr = sqrtf(gth - dzy2);
                    rxlo = max(xlo, (int)floorf((qx - rr - XMIN) * INV_CELL) - 1);
                    rxhi = min(xhi, (int)floorf((qx + rr - XMIN) * INV_CELL) + 1);
                }
                int rowbase = (z * GG + y) * GG;
                if (dzy == R) {
                    if (rxlo <= rxhi) scan_span(rowbase, rxlo, rxhi);
                } else {
                    int xa = cx - R, xb = cx + R;
                    if (xa >= 0 && xa >= rxlo && xa <= rxhi)
                        scan_span(rowbase, xa, xa);
                    if (xb < GG && xb >= rxlo && xb <= rxhi)
                        scan_span(rowbase, xb, xb);
                }
            }
        }
        if (gth < FINF) {
            float bx = fminf(qx - (XMIN + (float)(cx - R) * CELL),
                             (XMIN + (float)(cx + R + 1) * CELL) - qx);
            float by = fminf(qy - (XMIN + (float)(cy - R) * CELL),
                             (XMIN + (float)(cy + R + 1) * CELL) - qy);
            float bz = fminf(qz - (XMIN + (float)(cz - R) * CELL),
                             (XMIN + (float)(cz + R + 1) * CELL) - qz);
            float b = fmaxf(fminf(bx, fminf(by, bz)), 0.0f);
            if (gth <= b * b) break;
        }
    }

    if (lane < Kk) {
        g_knn[orig * Kk + lane] = li;
        atomicAdd(&g_deg[li], 1);       // fused out-degree
    }
}

// split-transpose of all three weight matrices in one launch
__global__ void convw_all_kernel(const float* __restrict__ W0,
                                 const float* __restrict__ W1,
                                 const float* __restrict__ W2) {
    int i = blockIdx.x * blockDim.x + threadIdx.x;
    if (i < Dd * Hh) {
        int k = i % Dd, n = i / Dd;
        g_w0s[(size_t)n * Dd + k] = pack_split(W0[(size_t)k * Hh + n]);
    }
    if (i < Hh * Hh) {
        int k = i % Hh, n = i / Hh;
        g_w1s[(size_t)n * Hh + k] = pack_split(W1[(size_t)k * Hh + n]);
        g_w2s[(size_t)n * Hh + k] = pack_split(W2[(size_t)k * Hh + n]);
    }
}

// agg in cell-sorted order; float4 vectorized; srcn computed inline; 512 threads
template <int F>
__global__ void __launch_bounds__(512) aggregate_kernel(
    const float* __restrict__ Hin, uint32_t* __restrict__ Sout) {
    const int TPN = F / 4;
    const int NPB = 512 / TPN;
    __shared__ int   jj[NPB][Kk];
    __shared__ float ss[NPB][Kk];
    int g = threadIdx.x / TPN;
    int t = threadIdx.x % TPN;
    int pos = blockIdx.x * NPB + g;
    bool ok = pos < Nn;
    int node = 0;
    if (ok) {
        node = g_ptIdx[pos];
        if (t < Kk) {
            int j = g_knn[node * Kk + t];
            jj[g][t] = j;
            ss[g][t] = rsqrtf(fmaxf((float)g_deg[j], 1.0f));
        }
    }
    __syncthreads();
    if (!ok) return;
    float4 acc = make_float4(0.f, 0.f, 0.f, 0.f);
#pragma unroll
    for (int k = 0; k < Kk; k++) {
        const float4* row = (const float4*)(Hin + (size_t)jj[g][k] * F);
        float4 v = row[t];
        float s = ss[g][k];
        acc.x = fmaf(v.x, s, acc.x);
        acc.y = fmaf(v.y, s, acc.y);
        acc.z = fmaf(v.z, s, acc.z);
        acc.w = fmaf(v.w, s, acc.w);
    }
    uint4 o;
    o.x = pack_split(acc.x * 0.25f);
    o.y = pack_split(acc.y * 0.25f);
    o.z = pack_split(acc.z * 0.25f);
    o.w = pack_split(acc.w * 0.25f);
    *(uint4*)(Sout + (size_t)node * F + t * 4) = o;
}

// ---------------- tensor-core GEMM (double-buffered) -----------------
// If wf != nullptr: fused final — instead of writing C, compute per-row
// partial dot of relu(acc + bias) with wf and write to part[colblock][row].
#define BM 128
#define BN 128
#define BK 16
#define LDA2 40

__global__ void __launch_bounds__(256, 2) mma_gemm_kernel(
    const uint32_t* __restrict__ A2, const uint32_t* __restrict__ B2,
    const float* __restrict__ bias, float* __restrict__ C,
    int M, int Kd, int Nc,
    const float* __restrict__ wf, float* __restrict__ part) {
    __shared__ __align__(16) uint16_t As[2][BM * LDA2];
    __shared__ __align__(16) uint16_t Bs[2][BN * LDA2];
    __shared__ float srow[BM];

    int t = threadIdx.x;
    int lane = t & 31;
    int wid = t >> 5;
    int m0 = blockIdx.y * BM;
    int n0 = blockIdx.x * BN;

    int wm = wid & 3;
    int wn = wid >> 2;
    int m_base = wm * 32;
    int n_base = wn * 64;

    uint32_t as_base = smem_u32(As);
    uint32_t bs_base = smem_u32(Bs);
    const uint32_t aBufStride = BM * LDA2 * 2;
    const uint32_t bBufStride = BN * LDA2 * 2;

    uint32_t aaddr[2], baddr[4];
#pragma unroll
    for (int f = 0; f < 2; f++) {
        int row = m_base + f * 16 + (lane & 7) + (lane & 8);
        int koff = (lane & 16) ? 16 : 0;
        aaddr[f] = as_base + row * (LDA2 * 2) + koff;
    }
#pragma unroll
    for (int p = 0; p < 4; p++) {
        int row = n_base + p * 16 + (lane & 7) + ((lane & 16) >> 1);
        int koff = (lane & 8) ? 16 : 0;
        baddr[p] = bs_base + row * (LDA2 * 2) + koff;
    }

    int fr0 = t >> 2, fq0 = t & 3;
    int fr1 = (t + 256) >> 2, fq1 = (t + 256) & 3;

    float acc[2][8][4];
#pragma unroll
    for (int f = 0; f < 2; f++)
#pragma unroll
        for (int nf = 0; nf < 8; nf++)
#pragma unroll
            for (int c = 0; c < 4; c++) acc[f][nf][c] = 0.0f;

    uint32_t* As32 = (uint32_t*)As;
    uint32_t* Bs32 = (uint32_t*)Bs;
    const int aBuf32 = BM * LDA2 / 2;
    const int bBuf32 = BN * LDA2 / 2;

    auto fetch = [&](int s, uint4* ra, uint4* rb) {
        int k0 = s * BK;
        int gm0 = m0 + fr0;
        ra[0] = (gm0 < M) ? *(const uint4*)(A2 + (size_t)gm0 * Kd + k0 + fq0 * 4)
                          : make_uint4(0u, 0u, 0u, 0u);
        int gm1 = m0 + fr1;
        ra[1] = (gm1 < M) ? *(const uint4*)(A2 + (size_t)gm1 * Kd + k0 + fq1 * 4)
                          : make_uint4(0u, 0u, 0u, 0u);
        rb[0] = *(const uint4*)(B2 + (size_t)(n0 + fr0) * Kd + k0 + fq0 * 4);
        rb[1] = *(const uint4*)(B2 + (size_t)(n0 + fr1) * Kd + k0 + fq1 * 4);
    };
    auto unp_store = [&](uint32_t* dst, int b32, uint4 d) {
        uint32_t h0 = d.x & 0xffffu, l0 = d.x >> 16;
        uint32_t h1 = d.y & 0xffffu, l1 = d.y >> 16;
        uint32_t h2 = d.z & 0xffffu, l2 = d.z >> 16;
        uint32_t h3 = d.w & 0xffffu, l3 = d.w >> 16;
        dst[b32 + 0] = h0 | (h1 << 16);
        dst[b32 + 1] = h2 | (h3 << 16);
        dst[b32 + 8] = l0 | (l1 << 16);
        dst[b32 + 9] = l2 | (l3 << 16);
    };
    auto store_buf = [&](int buf, uint4* ra, uint4* rb) {
        unp_store(As32 + buf * aBuf32, fr0 * (LDA2 / 2) + 2 * fq0, ra[0]);
        unp_store(As32 + buf * aBuf32, fr1 * (LDA2 / 2) + 2 * fq1, ra[1]);
        unp_store(Bs32 + buf * bBuf32, fr0 * (LDA2 / 2) + 2 * fq0, rb[0]);
        unp_store(Bs32 + buf * bBuf32, fr1 * (LDA2 / 2) + 2 * fq1, rb[1]);
    };
    auto compute = [&](int buf) {
        uint32_t aoff = buf * aBufStride;
        uint32_t boff = buf * bBufStride;
        uint32_t a_h[2][4], a_l[2][4], b[4][4];
#pragma unroll
        for (int f = 0; f < 2; f++) ldsm4(a_h[f], aaddr[f] + aoff);
#pragma unroll
        for (int p = 0; p < 4; p++) ldsm4(b[p], baddr[p] + boff);
#pragma unroll
        for (int f = 0; f < 2; f++)
#pragma unroll
            for (int p = 0; p < 4; p++) {
                mma16816(acc[f][2 * p],     a_h[f], b[p][0], b[p][1]);
                mma16816(acc[f][2 * p + 1], a_h[f], b[p][2], b[p][3]);
            }
#pragma unroll
        for (int f = 0; f < 2; f++) ldsm4(a_l[f], aaddr[f] + aoff + 32);
#pragma unroll
        for (int f = 0; f < 2; f++)
#pragma unroll
            for (int p = 0; p < 4; p++) {
                mma16816(acc[f][2 * p],     a_l[f], b[p][0], b[p][1]);
                mma16816(acc[f][2 * p + 1], a_l[f], b[p][2], b[p][3]);
            }
#pragma unroll
        for (int p = 0; p < 4; p++) ldsm4(b[p], baddr[p] + boff + 32);
#pragma unroll
        for (int f = 0; f < 2; f++)
#pragma unroll
            for (int p = 0; p < 4; p++) {
                mma16816(acc[f][2 * p],     a_h[f], b[p][0], b[p][1]);
                mma16816(acc[f][2 * p + 1], a_h[f], b[p][2], b[p][3]);
            }
    };

    const int steps = Kd / BK;
    uint4 ra[2], rb[2];
    fetch(0, ra, rb);
    store_buf(0, ra, rb);
    __syncthreads();
    for (int s = 0; s < steps; s++) {
        bool more = (s + 1 < steps);
        if (more) fetch(s + 1, ra, rb);
        compute(s & 1);
        if (more) {
            store_buf((s + 1) & 1, ra, rb);
            __syncthreads();
        }
    }

    if (wf == nullptr) {
        // normal epilogue: relu(acc + bias) -> C
#pragma unroll
        for (int f = 0; f < 2; f++) {
#pragma unroll
            for (int nf = 0; nf < 8; nf++) {
                int col = n0 + n_base + nf * 8 + 2 * (lane & 3);
                float2 bv = *(const float2*)&bias[col];
                int row = m0 + m_base + f * 16 + (lane >> 2);
                if (row < M) {
                    float2 o;
                    o.x = fmaxf(acc[f][nf][0] + bv.x, 0.0f);
                    o.y = fmaxf(acc[f][nf][1] + bv.y, 0.0f);
                    *(float2*)(C + (size_t)row * Nc + col) = o;
                }
                int row2 = row + 8;
                if (row2 < M) {
                    float2 o;
                    o.x = fmaxf(acc[f][nf][2] + bv.x, 0.0f);
                    o.y = fmaxf(acc[f][nf][3] + bv.y, 0.0f);
                    *(float2*)(C + (size_t)row2 * Nc + col) = o;
                }
            }
        }
    } else {
        // fused final: per-thread partial dot over its 16 cols, 4 rows
        float pr[4] = {0.f, 0.f, 0.f, 0.f};   // rows: f*16 + {lane>>2, lane>>2+8}
#pragma unroll
        for (int f = 0; f < 2; f++) {
#pragma unroll
            for (int nf = 0; nf < 8; nf++) {
                int col = n0 + n_base + nf * 8 + 2 * (lane & 3);
                float2 bv = *(const float2*)&bias[col];
                float2 wv = *(const float2*)&wf[col];
                float v0 = fmaxf(acc[f][nf][0] + bv.x, 0.0f);
                float v1 = fmaxf(acc[f][nf][1] + bv.y, 0.0f);
                float v2 = fmaxf(acc[f][nf][2] + bv.x, 0.0f);
                float v3 = fmaxf(acc[f][nf][3] + bv.y, 0.0f);
                pr[2 * f]     = fmaf(v0, wv.x, fmaf(v1, wv.y, pr[2 * f]));
                pr[2 * f + 1] = fmaf(v2, wv.x, fmaf(v3, wv.y, pr[2 * f + 1]));
            }
        }
        // quad reduce (lanes sharing lane>>2 hold same rows)
#pragma unroll
        for (int r = 0; r < 4; r++) {
            pr[r] += __shfl_xor_sync(FULLM, pr[r], 1);
            pr[r] += __shfl_xor_sync(FULLM, pr[r], 2);
        }
        // wn==0 warps stage, wn==1 warps add and write to global partials
        if ((lane & 3) == 0) {
            int rl0 = m_base + (lane >> 2);
            if (wn == 0) {
                srow[rl0]      = pr[0];
                srow[rl0 + 8]  = pr[1];
                srow[rl0 + 16] = pr[2];
                srow[rl0 + 24] = pr[3];
            }
        }
        __syncthreads();
        if (wn == 1 && (lane & 3) == 0) {
            int rl0 = m_base + (lane >> 2);
#pragma unroll
            for (int r = 0; r < 4; r++) {
                int rl = rl0 + r * 8;
                int row = m0 + rl;
                if (row < M)
                    part[(size_t)blockIdx.x * Nn + row] = pr[r] + srow[rl];
            }
        }
    }
}

// out[i] = sigmoid(part0[i] + part1[i] + bf)
__global__ void sigmoid_kernel(const float* __restrict__ part,
                               const float* __restrict__ bf,
                               float* __restrict__ out) {
    int i = blockIdx.x * blockDim.x + threadIdx.x;
    if (i >= Nn) return;
    float z = part[i] + part[Nn + i] + bf[0];
    out[i] = 1.0f / (1.0f + expf(-z));
}

// ---------------- host launcher --------------------
extern "C" void kernel_launch(void* const* d_in, const int* in_sizes, int n_in,
                              void* d_out, int out_size) {
    const float* x       = (const float*)d_in[0];
    const float* centers = (const float*)d_in[1];
    const float* W0      = (const float*)d_in[2];
    const float* b0      = (const float*)d_in[3];
    const float* W1      = (const float*)d_in[4];
    const float* b1      = (const float*)d_in[5];
    const float* W2      = (const float*)d_in[6];
    const float* b2      = (const float*)d_in[7];
    const float* Wf      = (const float*)d_in[8];
    const float* bf      = (const float*)d_in[9];
    float* out = (float*)d_out;
    (void)in_sizes; (void)n_in; (void)out_size;

    void *pH, *pS, *pW0, *pW1, *pW2, *pCnt, *pDeg, *pPart;
    cudaGetSymbolAddress(&pH, g_bufH);
    cudaGetSymbolAddress(&pS, g_bufS);
    cudaGetSymbolAddress(&pW0, g_w0s);
    cudaGetSymbolAddress(&pW1, g_w1s);
    cudaGetSymbolAddress(&pW2, g_w2s);
    cudaGetSymbolAddress(&pCnt, g_cellCnt);
    cudaGetSymbolAddress(&pDeg, g_deg);
    cudaGetSymbolAddress(&pPart, g_part);
    float*    Hbuf = (float*)pH;
    uint32_t* Sbuf = (uint32_t*)pS;
    float*    Part = (float*)pPart;

    cudaMemsetAsync(pCnt, 0, NC * sizeof(int));
    cudaMemsetAsync(pDeg, 0, Nn * sizeof(int));
    convw_all_kernel<<<(Hh * Hh + 255) / 256, 256>>>(W0, W1, W2);
    assign_kernel<<<(Nn + 255) / 256, 256>>>(centers);
    scan_kernel<<<1, 1024>>>();
    scatter_kernel<<<(Nn + 255) / 256, 256>>>(centers);
    knn_kernel<<<(Nn * 32 + 255) / 256, 256>>>();

    dim3 ggrid(Hh / BN, (Nn + BM - 1) / BM);

    // layer 0  (F=128: 16 nodes/block at 512 threads)
    aggregate_kernel<Dd><<<(Nn + 15) / 16, 512>>>(x, Sbuf);
    mma_gemm_kernel<<<ggrid, 256>>>(Sbuf, (uint32_t*)pW0, b0, Hbuf, Nn, Dd, Hh,
                                    nullptr, nullptr);

    // layer 1  (F=256: 8 nodes/block)
    aggregate_kernel<Hh><<<(Nn + 7) / 8, 512>>>(Hbuf, Sbuf);
    mma_gemm_kernel<<<ggrid, 256>>>(Sbuf, (uint32_t*)pW1, b1, Hbuf, Nn, Hh, Hh,
                                    nullptr, nullptr);

    // layer 2 + fused final dot
    aggregate_kernel<Hh><<<(Nn + 7) / 8, 512>>>(Hbuf, Sbuf);
    mma_gemm_kernel<<<ggrid, 256>>>(Sbuf, (uint32_t*)pW2, b2, nullptr, Nn, Hh, Hh,
                                    Wf, Part);

    // sigmoid
    sigmoid_kernel<<<(Nn + 255) / 256, 256>>>(Part, bf, out);
}